// round 1
// baseline (speedup 1.0000x reference)
#include <cuda_runtime.h>
#include <math.h>

#define U_NUM 100000
#define I_NUM 50000
#define N_NUM 150000
#define E_NUM 1200000
#define D 64
#define F_DIM 384
#define EPS 1e-8f

// Scratch (allocation-free rule: __device__ globals)
__device__ float g_ego[(size_t)N_NUM * D];
__device__ float g_bufA[(size_t)N_NUM * D];
__device__ float g_bufB[(size_t)N_NUM * D];
__device__ float g_invn[N_NUM];

// ---------------- user ego init: ego = user_fea + sum(g_emb_u, 0); acc = ego
__global__ void k_init_user(const float* __restrict__ user_fea,
                            const float* __restrict__ gu,
                            float* __restrict__ ego,
                            float* __restrict__ acc) {
    int warp = (blockIdx.x * blockDim.x + threadIdx.x) >> 5;
    int lane = threadIdx.x & 31;
    if (warp >= U_NUM) return;
    int d0 = lane * 2;
    float s0 = gu[d0]     + gu[D + d0]     + gu[2 * D + d0];
    float s1 = gu[d0 + 1] + gu[D + d0 + 1] + gu[2 * D + d0 + 1];
    float2 v = ((const float2*)(user_fea + (size_t)warp * D))[lane];
    v.x += s0; v.y += s1;
    ((float2*)(ego + (size_t)warp * D))[lane] = v;
    ((float2*)(acc + (size_t)warp * D))[lane] = v;
}

// ---------------- item ego init: ego = tanh(item_fea @ W^T + b) + sum(g_emb_i, 0)
#define BM 128
#define BN 64
#define BK 32

__global__ __launch_bounds__(256) void k_item_gemm(
    const float* __restrict__ A,     // [I_NUM, F_DIM]
    const float* __restrict__ W,     // [D, F_DIM]
    const float* __restrict__ bias,  // [D]
    const float* __restrict__ gi,    // [3, D]
    float* __restrict__ ego,
    float* __restrict__ acc) {
    __shared__ float As[BK][BM + 1];
    __shared__ float Bs[BK][BN + 1];
    int t = threadIdx.x;
    int tx = t & 15, ty = t >> 4;
    int r0 = blockIdx.x * BM;

    float accr[8][4];
    #pragma unroll
    for (int i = 0; i < 8; i++)
        #pragma unroll
        for (int j = 0; j < 4; j++) accr[i][j] = 0.f;

    for (int k0 = 0; k0 < F_DIM; k0 += BK) {
        #pragma unroll
        for (int s = 0; s < 16; s++) {
            int idx = t + s * 256;
            int row = idx >> 5, k = idx & 31;
            int gr = r0 + row;
            As[k][row] = (gr < I_NUM) ? A[(size_t)gr * F_DIM + k0 + k] : 0.f;
        }
        #pragma unroll
        for (int s = 0; s < 8; s++) {
            int idx = t + s * 256;
            int n = idx >> 5, k = idx & 31;
            Bs[k][n] = W[(size_t)n * F_DIM + k0 + k];
        }
        __syncthreads();
        #pragma unroll
        for (int kk = 0; kk < BK; kk++) {
            float a[8], b[4];
            #pragma unroll
            for (int i = 0; i < 8; i++) a[i] = As[kk][ty * 8 + i];
            #pragma unroll
            for (int j = 0; j < 4; j++) b[j] = Bs[kk][tx * 4 + j];
            #pragma unroll
            for (int i = 0; i < 8; i++)
                #pragma unroll
                for (int j = 0; j < 4; j++)
                    accr[i][j] = fmaf(a[i], b[j], accr[i][j]);
        }
        __syncthreads();
    }

    #pragma unroll
    for (int j = 0; j < 4; j++) {
        int n = tx * 4 + j;
        float bn = bias[n];
        float sn = gi[n] + gi[D + n] + gi[2 * D + n];
        #pragma unroll
        for (int i = 0; i < 8; i++) {
            int r = r0 + ty * 8 + i;
            if (r < I_NUM) {
                float v = tanhf(accr[i][j] + bn) + sn;
                size_t off = (size_t)(U_NUM + r) * D + n;
                ego[off] = v;
                acc[off] = v;
            }
        }
    }
}

// ---------------- precompute 1 / max(||ego_row||, eps)
__global__ void k_norm(const float* __restrict__ ego, float* __restrict__ invn) {
    int warp = (blockIdx.x * blockDim.x + threadIdx.x) >> 5;
    int lane = threadIdx.x & 31;
    if (warp >= N_NUM) return;
    float2 v = ((const float2*)(ego + (size_t)warp * D))[lane];
    float ss = v.x * v.x + v.y * v.y;
    #pragma unroll
    for (int o = 16; o; o >>= 1) ss += __shfl_xor_sync(0xffffffffu, ss, o);
    if (lane == 0) invn[warp] = 1.0f / fmaxf(sqrtf(ss), EPS);
}

// ---------------- edge scatter: y[row] += val * x[col]  (8 threads per edge)
__device__ __forceinline__ void red_add_v4(float* p, float a, float b, float c, float d) {
    asm volatile("red.global.add.v4.f32 [%0], {%1,%2,%3,%4};"
                 :: "l"(p), "f"(a), "f"(b), "f"(c), "f"(d) : "memory");
}

__global__ __launch_bounds__(256) void k_scatter(
    const float* __restrict__ x, float* __restrict__ y,
    const int* __restrict__ rows, const int* __restrict__ cols,
    const float* __restrict__ vals) {
    int g = blockIdx.x * blockDim.x + threadIdx.x;
    int e = g >> 3;
    if (e >= E_NUM) return;
    int t = g & 7;
    int c = __ldg(cols + e);
    int r = __ldg(rows + e);
    float v = __ldg(vals + e);
    const float4* xs = (const float4*)(x + (size_t)c * D) + t * 2;
    float4 a = __ldg(xs);
    float4 b = __ldg(xs + 1);
    float* dst = y + (size_t)r * D + t * 8;
    red_add_v4(dst,     a.x * v, a.y * v, a.z * v, a.w * v);
    red_add_v4(dst + 4, b.x * v, b.y * v, b.z * v, b.w * v);
}

// ---------------- cosine reweight + accumulate (warp per row)
__global__ void k_weight(float* __restrict__ y,
                         const float* __restrict__ ego,
                         const float* __restrict__ invn,
                         float* __restrict__ acc) {
    int warp = (blockIdx.x * blockDim.x + threadIdx.x) >> 5;
    int lane = threadIdx.x & 31;
    if (warp >= N_NUM) return;
    size_t base = (size_t)warp * D;
    float2 yv = ((const float2*)(y + base))[lane];
    float2 ev = ((const float2*)(ego + base))[lane];
    float dot = yv.x * ev.x + yv.y * ev.y;
    float ss  = yv.x * yv.x + yv.y * yv.y;
    #pragma unroll
    for (int o = 16; o; o >>= 1) {
        dot += __shfl_xor_sync(0xffffffffu, dot, o);
        ss  += __shfl_xor_sync(0xffffffffu, ss, o);
    }
    float w = dot * invn[warp] * (1.0f / fmaxf(sqrtf(ss), EPS));
    yv.x *= w; yv.y *= w;
    ((float2*)(y + base))[lane] = yv;
    float2* ap = (float2*)(acc + base) + lane;
    float2 av = *ap;
    av.x += yv.x; av.y += yv.y;
    *ap = av;
}

extern "C" void kernel_launch(void* const* d_in, const int* in_sizes, int n_in,
                              void* d_out, int out_size) {
    const int*   adj_row  = (const int*)d_in[0];
    const int*   adj_col  = (const int*)d_in[1];
    const float* adj_val  = (const float*)d_in[2];
    const float* user_fea = (const float*)d_in[3];
    const float* item_fea = (const float*)d_in[4];
    const float* g_emb_u  = (const float*)d_in[5];
    const float* g_emb_i  = (const float*)d_in[6];
    const float* mlp_w    = (const float*)d_in[7];
    const float* mlp_b    = (const float*)d_in[8];
    float* acc = (float*)d_out;

    float *ego_p, *bufA, *bufB, *invn_p;
    cudaGetSymbolAddress((void**)&ego_p,  g_ego);
    cudaGetSymbolAddress((void**)&bufA,   g_bufA);
    cudaGetSymbolAddress((void**)&bufB,   g_bufB);
    cudaGetSymbolAddress((void**)&invn_p, g_invn);

    k_init_user<<<(U_NUM + 7) / 8, 256>>>(user_fea, g_emb_u, ego_p, acc);
    k_item_gemm<<<(I_NUM + BM - 1) / BM, 256>>>(item_fea, mlp_w, mlp_b, g_emb_i, ego_p, acc);
    k_norm<<<(N_NUM + 7) / 8, 256>>>(ego_p, invn_p);

    const float* xin = ego_p;
    float* bufs[2] = {bufA, bufB};
    for (int l = 0; l < 4; l++) {
        float* yb = bufs[l & 1];
        cudaMemsetAsync(yb, 0, (size_t)N_NUM * D * sizeof(float));
        k_scatter<<<(E_NUM * 8 + 255) / 256, 256>>>(xin, yb, adj_row, adj_col, adj_val);
        k_weight<<<(N_NUM + 7) / 8, 256>>>(yb, ego_p, invn_p, acc);
        xin = yb;
    }
}

// round 2
// speedup vs baseline: 1.3386x; 1.3386x over previous
#include <cuda_runtime.h>
#include <math.h>

#define U_NUM 100000
#define I_NUM 50000
#define N_NUM 150000
#define E_NUM 1200000
#define D 64
#define F_DIM 384
#define EPS 1e-8f
#define ELL_W 64   // slot cap; max degree of Poisson(8) over 150K rows is ~30

// Scratch (allocation-free rule: __device__ globals)
__device__ float g_ego[(size_t)N_NUM * D];
__device__ float g_bufA[(size_t)N_NUM * D];
__device__ float g_bufB[(size_t)N_NUM * D];
__device__ int   g_cnt[N_NUM];
__device__ int   g_ellc[(size_t)N_NUM * ELL_W];
__device__ float g_ellv[(size_t)N_NUM * ELL_W];

// ---------------- ELL build: slot = atomicAdd(cnt[row]); store (col, val)
__global__ __launch_bounds__(256) void k_build(
    const int* __restrict__ rows, const int* __restrict__ cols,
    const float* __restrict__ vals,
    int* __restrict__ cnt, int* __restrict__ ellc, float* __restrict__ ellv) {
    int e = blockIdx.x * blockDim.x + threadIdx.x;
    if (e >= E_NUM) return;
    int r = __ldg(rows + e);
    int slot = atomicAdd(cnt + r, 1);
    if (slot < ELL_W) {
        size_t p = (size_t)r * ELL_W + slot;
        ellc[p] = __ldg(cols + e);
        ellv[p] = __ldg(vals + e);
    }
}

// ---------------- user ego init: ego = user_fea + sum(g_emb_u, 0); acc = ego
__global__ void k_init_user(const float* __restrict__ user_fea,
                            const float* __restrict__ gu,
                            float* __restrict__ ego,
                            float* __restrict__ acc) {
    int warp = (blockIdx.x * blockDim.x + threadIdx.x) >> 5;
    int lane = threadIdx.x & 31;
    if (warp >= U_NUM) return;
    int d0 = lane * 2;
    float s0 = gu[d0]     + gu[D + d0]     + gu[2 * D + d0];
    float s1 = gu[d0 + 1] + gu[D + d0 + 1] + gu[2 * D + d0 + 1];
    float2 v = ((const float2*)(user_fea + (size_t)warp * D))[lane];
    v.x += s0; v.y += s1;
    ((float2*)(ego + (size_t)warp * D))[lane] = v;
    ((float2*)(acc + (size_t)warp * D))[lane] = v;
}

// ---------------- item ego init: ego = tanh(item_fea @ W^T + b) + sum(g_emb_i, 0)
#define BM 128
#define BK 32

__global__ __launch_bounds__(256) void k_item_gemm(
    const float* __restrict__ A,     // [I_NUM, F_DIM]
    const float* __restrict__ W,     // [D, F_DIM]
    const float* __restrict__ bias,  // [D]
    const float* __restrict__ gi,    // [3, D]
    float* __restrict__ ego,
    float* __restrict__ acc) {
    __shared__ float As[BK][BM + 1];
    __shared__ float Bs[BK][D + 1];
    int t = threadIdx.x;
    int tx = t & 15, ty = t >> 4;
    int r0 = blockIdx.x * BM;

    float accr[8][4];
    #pragma unroll
    for (int i = 0; i < 8; i++)
        #pragma unroll
        for (int j = 0; j < 4; j++) accr[i][j] = 0.f;

    for (int k0 = 0; k0 < F_DIM; k0 += BK) {
        #pragma unroll
        for (int s = 0; s < 16; s++) {
            int idx = t + s * 256;
            int row = idx >> 5, k = idx & 31;
            int gr = r0 + row;
            As[k][row] = (gr < I_NUM) ? A[(size_t)gr * F_DIM + k0 + k] : 0.f;
        }
        #pragma unroll
        for (int s = 0; s < 8; s++) {
            int idx = t + s * 256;
            int n = idx >> 5, k = idx & 31;
            Bs[k][n] = W[(size_t)n * F_DIM + k0 + k];
        }
        __syncthreads();
        #pragma unroll
        for (int kk = 0; kk < BK; kk++) {
            float a[8], b[4];
            #pragma unroll
            for (int i = 0; i < 8; i++) a[i] = As[kk][ty * 8 + i];
            #pragma unroll
            for (int j = 0; j < 4; j++) b[j] = Bs[kk][tx * 4 + j];
            #pragma unroll
            for (int i = 0; i < 8; i++)
                #pragma unroll
                for (int j = 0; j < 4; j++)
                    accr[i][j] = fmaf(a[i], b[j], accr[i][j]);
        }
        __syncthreads();
    }

    #pragma unroll
    for (int j = 0; j < 4; j++) {
        int n = tx * 4 + j;
        float bn = bias[n];
        float sn = gi[n] + gi[D + n] + gi[2 * D + n];
        #pragma unroll
        for (int i = 0; i < 8; i++) {
            int r = r0 + ty * 8 + i;
            if (r < I_NUM) {
                float v = tanhf(accr[i][j] + bn) + sn;
                size_t off = (size_t)(U_NUM + r) * D + n;
                ego[off] = v;
                acc[off] = v;
            }
        }
    }
}

// ---------------- fused layer: y = w * (A x);  acc += y  (warp per row, no atomics)
__global__ __launch_bounds__(256) void k_layer(
    const float* __restrict__ x, float* __restrict__ y,
    const int* __restrict__ cnt, const int* __restrict__ ellc,
    const float* __restrict__ ellv,
    const float* __restrict__ ego, float* __restrict__ acc) {
    int row = (blockIdx.x * blockDim.x + threadIdx.x) >> 5;
    int lane = threadIdx.x & 31;
    if (row >= N_NUM) return;
    int c = __ldg(cnt + row);
    float yx = 0.f, yy = 0.f;
    size_t ebase = (size_t)row * ELL_W;
    for (int b = 0; b < c; b += 32) {
        int n = min(c - b, 32);
        int col = 0; float v = 0.f;
        if (lane < n) {
            col = __ldg(ellc + ebase + b + lane);
            v   = __ldg(ellv + ebase + b + lane);
        }
        #pragma unroll 4
        for (int e = 0; e < n; e++) {
            int   cc = __shfl_sync(0xffffffffu, col, e);
            float vv = __shfl_sync(0xffffffffu, v, e);
            float2 xv = __ldg((const float2*)(x + (size_t)cc * D) + lane);
            yx = fmaf(vv, xv.x, yx);
            yy = fmaf(vv, xv.y, yy);
        }
    }
    size_t base = (size_t)row * D;
    float2 ev = __ldg((const float2*)(ego + base) + lane);
    float dot = yx * ev.x + yy * ev.y;
    float ssy = yx * yx + yy * yy;
    float sse = ev.x * ev.x + ev.y * ev.y;
    #pragma unroll
    for (int o = 16; o; o >>= 1) {
        dot += __shfl_xor_sync(0xffffffffu, dot, o);
        ssy += __shfl_xor_sync(0xffffffffu, ssy, o);
        sse += __shfl_xor_sync(0xffffffffu, sse, o);
    }
    float w = dot / (fmaxf(sqrtf(ssy), EPS) * fmaxf(sqrtf(sse), EPS));
    yx *= w; yy *= w;
    float2 yo; yo.x = yx; yo.y = yy;
    ((float2*)(y + base))[lane] = yo;
    float2* ap = (float2*)(acc + base) + lane;
    float2 av = *ap;
    av.x += yx; av.y += yy;
    *ap = av;
}

extern "C" void kernel_launch(void* const* d_in, const int* in_sizes, int n_in,
                              void* d_out, int out_size) {
    const int*   adj_row  = (const int*)d_in[0];
    const int*   adj_col  = (const int*)d_in[1];
    const float* adj_val  = (const float*)d_in[2];
    const float* user_fea = (const float*)d_in[3];
    const float* item_fea = (const float*)d_in[4];
    const float* g_emb_u  = (const float*)d_in[5];
    const float* g_emb_i  = (const float*)d_in[6];
    const float* mlp_w    = (const float*)d_in[7];
    const float* mlp_b    = (const float*)d_in[8];
    float* acc = (float*)d_out;

    float *ego_p, *bufA, *bufB, *ellv_p;
    int *cnt_p, *ellc_p;
    cudaGetSymbolAddress((void**)&ego_p,  g_ego);
    cudaGetSymbolAddress((void**)&bufA,   g_bufA);
    cudaGetSymbolAddress((void**)&bufB,   g_bufB);
    cudaGetSymbolAddress((void**)&cnt_p,  g_cnt);
    cudaGetSymbolAddress((void**)&ellc_p, g_ellc);
    cudaGetSymbolAddress((void**)&ellv_p, g_ellv);

    // Build padded ELL from COO (per replay; static adjacency)
    cudaMemsetAsync(cnt_p, 0, N_NUM * sizeof(int));
    k_build<<<(E_NUM + 255) / 256, 256>>>(adj_row, adj_col, adj_val,
                                          cnt_p, ellc_p, ellv_p);

    // Ego embeddings
    k_init_user<<<(U_NUM + 7) / 8, 256>>>(user_fea, g_emb_u, ego_p, acc);
    k_item_gemm<<<(I_NUM + BM - 1) / BM, 256>>>(item_fea, mlp_w, mlp_b, g_emb_i, ego_p, acc);

    // 4 fused propagation layers (gather SpMM + cosine reweight + accumulate)
    const float* xin = ego_p;
    float* bufs[2] = {bufA, bufB};
    for (int l = 0; l < 4; l++) {
        float* yb = bufs[l & 1];
        k_layer<<<(N_NUM + 7) / 8, 256>>>(xin, yb, cnt_p, ellc_p, ellv_p, ego_p, acc);
        xin = yb;
    }
}

// round 3
// speedup vs baseline: 1.6078x; 1.2011x over previous
#include <cuda_runtime.h>
#include <math.h>

#define U_NUM 100000
#define I_NUM 50000
#define N_NUM 150000
#define E_NUM 1200000
#define D 64
#define F_DIM 384
#define EPS 1e-8f
#define ELL_W 64

// Scratch (allocation-free rule: __device__ globals)
__device__ float g_ego[(size_t)N_NUM * D];
__device__ float g_buf0[(size_t)N_NUM * D];
__device__ float g_buf1[(size_t)N_NUM * D];
__device__ float g_buf2[(size_t)N_NUM * D];
__device__ float g_buf3[(size_t)N_NUM * D];
__device__ int   g_cnt[N_NUM];
__device__ int   g_ellc[(size_t)N_NUM * ELL_W];
__device__ float g_ellv[(size_t)N_NUM * ELL_W];

// ---------------- f32x2 packed helpers (Blackwell)
__device__ __forceinline__ unsigned long long pack2(float lo, float hi) {
    unsigned long long r;
    asm("mov.b64 %0, {%1,%2};" : "=l"(r) : "f"(lo), "f"(hi));
    return r;
}
__device__ __forceinline__ void unpack2(unsigned long long p, float& lo, float& hi) {
    asm("mov.b64 {%0,%1}, %2;" : "=f"(lo), "=f"(hi) : "l"(p));
}
__device__ __forceinline__ void fma2(unsigned long long& d,
                                     unsigned long long a, unsigned long long b) {
    asm("fma.rn.f32x2 %0, %1, %2, %3;" : "=l"(d) : "l"(a), "l"(b), "l"(d));
}

// ---------------- ELL build
__global__ __launch_bounds__(256) void k_build(
    const int* __restrict__ rows, const int* __restrict__ cols,
    const float* __restrict__ vals,
    int* __restrict__ cnt, int* __restrict__ ellc, float* __restrict__ ellv) {
    int e = blockIdx.x * blockDim.x + threadIdx.x;
    if (e >= E_NUM) return;
    int r = __ldg(rows + e);
    int slot = atomicAdd(cnt + r, 1);
    if (slot < ELL_W) {
        size_t p = (size_t)r * ELL_W + slot;
        ellc[p] = __ldg(cols + e);
        ellv[p] = __ldg(vals + e);
    }
}

// ---------------- user ego init: ego = user_fea + sum(g_emb_u, 0)
__global__ void k_init_user(const float* __restrict__ user_fea,
                            const float* __restrict__ gu,
                            float* __restrict__ ego) {
    int warp = (blockIdx.x * blockDim.x + threadIdx.x) >> 5;
    int lane = threadIdx.x & 31;
    if (warp >= U_NUM) return;
    int d0 = lane * 2;
    float s0 = gu[d0]     + gu[D + d0]     + gu[2 * D + d0];
    float s1 = gu[d0 + 1] + gu[D + d0 + 1] + gu[2 * D + d0 + 1];
    float2 v = ((const float2*)(user_fea + (size_t)warp * D))[lane];
    v.x += s0; v.y += s1;
    ((float2*)(ego + (size_t)warp * D))[lane] = v;
}

// ---------------- item ego init: ego = tanh(item_fea @ W^T + b) + sum(g_emb_i, 0)
// f32x2 packed-FMA GEMM: 128x64 block tile, 256 threads, exact fp32.
#define BM 128
#define BK 32

__global__ __launch_bounds__(256) void k_item_gemm(
    const float* __restrict__ A,     // [I_NUM, F_DIM]
    const float* __restrict__ W,     // [D, F_DIM]
    const float* __restrict__ bias,  // [D]
    const float* __restrict__ gi,    // [3, D]
    float* __restrict__ ego) {
    __shared__ float As[BK][BM + 2];
    __shared__ float Bs[BK][D + 2];
    int t = threadIdx.x;
    int tx = t & 15, ty = t >> 4;
    int r0 = blockIdx.x * BM;

    // acc2[i][p]: rows ty*8+i, col pair (tx*4 + 2p, tx*4 + 2p + 1)
    unsigned long long acc2[8][2];
    #pragma unroll
    for (int i = 0; i < 8; i++) { acc2[i][0] = 0ull; acc2[i][1] = 0ull; }

    for (int k0 = 0; k0 < F_DIM; k0 += BK) {
        #pragma unroll
        for (int s = 0; s < 16; s++) {
            int idx = t + s * 256;
            int row = idx >> 5, k = idx & 31;
            int gr = r0 + row;
            As[k][row] = (gr < I_NUM) ? A[(size_t)gr * F_DIM + k0 + k] : 0.f;
        }
        #pragma unroll
        for (int s = 0; s < 8; s++) {
            int idx = t + s * 256;
            int n = idx >> 5, k = idx & 31;
            Bs[k][n] = W[(size_t)n * F_DIM + k0 + k];
        }
        __syncthreads();
        #pragma unroll
        for (int kk = 0; kk < BK; kk++) {
            unsigned long long b0 = *(const unsigned long long*)&Bs[kk][tx * 4];
            unsigned long long b1 = *(const unsigned long long*)&Bs[kk][tx * 4 + 2];
            #pragma unroll
            for (int i = 0; i < 8; i++) {
                float a = As[kk][ty * 8 + i];
                unsigned long long a2 = pack2(a, a);
                fma2(acc2[i][0], a2, b0);
                fma2(acc2[i][1], a2, b1);
            }
        }
        __syncthreads();
    }

    #pragma unroll
    for (int p = 0; p < 2; p++) {
        int n = tx * 4 + 2 * p;
        float bn0 = bias[n],     sn0 = gi[n]     + gi[D + n]     + gi[2 * D + n];
        float bn1 = bias[n + 1], sn1 = gi[n + 1] + gi[D + n + 1] + gi[2 * D + n + 1];
        #pragma unroll
        for (int i = 0; i < 8; i++) {
            int r = r0 + ty * 8 + i;
            if (r < I_NUM) {
                float c0, c1;
                unpack2(acc2[i][p], c0, c1);
                size_t off = (size_t)(U_NUM + r) * D + n;
                ego[off]     = tanhf(c0 + bn0) + sn0;
                ego[off + 1] = tanhf(c1 + bn1) + sn1;
            }
        }
    }
}

// ---------------- fused layer: y = w * (A x)   (half-warp per row, no atomics, no acc)
__global__ __launch_bounds__(256) void k_layer(
    const float* __restrict__ x, float* __restrict__ y,
    const int* __restrict__ cnt, const int* __restrict__ ellc,
    const float* __restrict__ ellv,
    const float* __restrict__ ego) {
    int warp = (blockIdx.x * blockDim.x + threadIdx.x) >> 5;
    int lane = threadIdx.x & 31;
    int half = lane >> 4;          // 0 or 1
    int hl   = lane & 15;          // lane within half
    int row  = warp * 2 + half;
    if (row >= N_NUM) return;
    unsigned hmask = 0xFFFFu << (half * 16);

    int c = min(__ldg(cnt + row), ELL_W);
    // nmax across the warp (both halves run the same #batches)
    int cmax = max(c, __shfl_xor_sync(0xffffffffu, c, 16));

    float4 acc = make_float4(0.f, 0.f, 0.f, 0.f);
    size_t ebase = (size_t)row * ELL_W;

    for (int b = 0; b < cmax; b += 16) {
        int n    = min(c - b, 16);          // may be <= 0 for this half
        int nmax = min(cmax - b, 16);
        int col = 0; float v = 0.f;
        if (hl < n) {
            col = __ldg(ellc + ebase + b + hl);
            v   = __ldg(ellv + ebase + b + hl);
        }
        #pragma unroll 4
        for (int e = 0; e < nmax; e++) {
            if (e < n) {
                int   cc = __shfl_sync(hmask, col, e, 16);
                float vv = __shfl_sync(hmask, v,   e, 16);
                float4 xv = __ldg((const float4*)(x + (size_t)cc * D) + hl);
                acc.x = fmaf(vv, xv.x, acc.x);
                acc.y = fmaf(vv, xv.y, acc.y);
                acc.z = fmaf(vv, xv.z, acc.z);
                acc.w = fmaf(vv, xv.w, acc.w);
            }
        }
    }

    size_t base = (size_t)row * D;
    float4 ev = __ldg((const float4*)(ego + base) + hl);
    float dot = acc.x * ev.x + acc.y * ev.y + acc.z * ev.z + acc.w * ev.w;
    float ssy = acc.x * acc.x + acc.y * acc.y + acc.z * acc.z + acc.w * acc.w;
    float sse = ev.x * ev.x + ev.y * ev.y + ev.z * ev.z + ev.w * ev.w;
    #pragma unroll
    for (int o = 8; o; o >>= 1) {
        dot += __shfl_xor_sync(0xffffffffu, dot, o);
        ssy += __shfl_xor_sync(0xffffffffu, ssy, o);
        sse += __shfl_xor_sync(0xffffffffu, sse, o);
    }
    float w = dot / (fmaxf(sqrtf(ssy), EPS) * fmaxf(sqrtf(sse), EPS));
    acc.x *= w; acc.y *= w; acc.z *= w; acc.w *= w;
    ((float4*)(y + base))[hl] = acc;
}

// ---------------- final combine: acc = ego + y1 + y2 + y3 + y4
__global__ __launch_bounds__(256) void k_combine(
    const float* __restrict__ ego,
    const float* __restrict__ y0, const float* __restrict__ y1,
    const float* __restrict__ y2, const float* __restrict__ y3,
    float* __restrict__ acc) {
    size_t i = (size_t)blockIdx.x * blockDim.x + threadIdx.x;
    if (i >= (size_t)N_NUM * D / 4) return;
    float4 e = __ldg((const float4*)ego + i);
    float4 a = __ldg((const float4*)y0 + i);
    float4 b = __ldg((const float4*)y1 + i);
    float4 c = __ldg((const float4*)y2 + i);
    float4 d = __ldg((const float4*)y3 + i);
    float4 o;
    o.x = e.x + a.x + b.x + c.x + d.x;
    o.y = e.y + a.y + b.y + c.y + d.y;
    o.z = e.z + a.z + b.z + c.z + d.z;
    o.w = e.w + a.w + b.w + c.w + d.w;
    ((float4*)acc)[i] = o;
}

extern "C" void kernel_launch(void* const* d_in, const int* in_sizes, int n_in,
                              void* d_out, int out_size) {
    const int*   adj_row  = (const int*)d_in[0];
    const int*   adj_col  = (const int*)d_in[1];
    const float* adj_val  = (const float*)d_in[2];
    const float* user_fea = (const float*)d_in[3];
    const float* item_fea = (const float*)d_in[4];
    const float* g_emb_u  = (const float*)d_in[5];
    const float* g_emb_i  = (const float*)d_in[6];
    const float* mlp_w    = (const float*)d_in[7];
    const float* mlp_b    = (const float*)d_in[8];
    float* acc = (float*)d_out;

    float *ego_p, *ellv_p, *bufs[4];
    int *cnt_p, *ellc_p;
    cudaGetSymbolAddress((void**)&ego_p,    g_ego);
    cudaGetSymbolAddress((void**)&bufs[0],  g_buf0);
    cudaGetSymbolAddress((void**)&bufs[1],  g_buf1);
    cudaGetSymbolAddress((void**)&bufs[2],  g_buf2);
    cudaGetSymbolAddress((void**)&bufs[3],  g_buf3);
    cudaGetSymbolAddress((void**)&cnt_p,    g_cnt);
    cudaGetSymbolAddress((void**)&ellc_p,   g_ellc);
    cudaGetSymbolAddress((void**)&ellv_p,   g_ellv);

    // Build padded ELL from COO
    cudaMemsetAsync(cnt_p, 0, N_NUM * sizeof(int));
    k_build<<<(E_NUM + 255) / 256, 256>>>(adj_row, adj_col, adj_val,
                                          cnt_p, ellc_p, ellv_p);

    // Ego embeddings
    k_init_user<<<(U_NUM + 7) / 8, 256>>>(user_fea, g_emb_u, ego_p);
    k_item_gemm<<<(I_NUM + BM - 1) / BM, 256>>>(item_fea, mlp_w, mlp_b, g_emb_i, ego_p);

    // 4 fused propagation layers (2 rows per warp)
    const float* xin = ego_p;
    for (int l = 0; l < 4; l++) {
        k_layer<<<(N_NUM / 2 + 7) / 8, 256>>>(xin, bufs[l], cnt_p, ellc_p, ellv_p, ego_p);
        xin = bufs[l];
    }

    // acc = ego + sum(layers)
    size_t nv = (size_t)N_NUM * D / 4;
    k_combine<<<(unsigned)((nv + 255) / 256), 256>>>(ego_p, bufs[0], bufs[1],
                                                     bufs[2], bufs[3], acc);
}

// round 5
// speedup vs baseline: 1.8995x; 1.1814x over previous
#include <cuda_runtime.h>
#include <math.h>

#define U_NUM 100000
#define I_NUM 50000
#define N_NUM 150000
#define E_NUM 1200000
#define D 64
#define F_DIM 384
#define EPS 1e-8f
#define ELL_W 64

// Scratch (allocation-free rule: __device__ globals)
__device__ float g_ego[(size_t)N_NUM * D];
__device__ float g_buf0[(size_t)N_NUM * D];
__device__ float g_buf1[(size_t)N_NUM * D];
__device__ float g_buf2[(size_t)N_NUM * D];
__device__ int   g_cnt[N_NUM];
__device__ int2  g_elle[(size_t)N_NUM * ELL_W];   // packed (col, val-bits)

// ---------------- f32x2 packed helpers (Blackwell)
__device__ __forceinline__ unsigned long long pack2(float lo, float hi) {
    unsigned long long r;
    asm("mov.b64 %0, {%1,%2};" : "=l"(r) : "f"(lo), "f"(hi));
    return r;
}
__device__ __forceinline__ void unpack2(unsigned long long p, float& lo, float& hi) {
    asm("mov.b64 {%0,%1}, %2;" : "=f"(lo), "=f"(hi) : "l"(p));
}
__device__ __forceinline__ void fma2(unsigned long long& d,
                                     unsigned long long a, unsigned long long b) {
    asm("fma.rn.f32x2 %0, %1, %2, %3;" : "=l"(d) : "l"(a), "l"(b), "l"(d));
}

// ---------------- ELL build (packed col+val)
__global__ __launch_bounds__(256) void k_build(
    const int* __restrict__ rows, const int* __restrict__ cols,
    const float* __restrict__ vals,
    int* __restrict__ cnt, int2* __restrict__ elle) {
    int e = blockIdx.x * blockDim.x + threadIdx.x;
    if (e >= E_NUM) return;
    int r = __ldg(rows + e);
    int slot = atomicAdd(cnt + r, 1);
    if (slot < ELL_W) {
        int2 p;
        p.x = __ldg(cols + e);
        p.y = __float_as_int(__ldg(vals + e));
        elle[(size_t)r * ELL_W + slot] = p;
    }
}

// ---------------- user ego init: ego = user_fea + sum(g_emb_u, 0)
__global__ void k_init_user(const float* __restrict__ user_fea,
                            const float* __restrict__ gu,
                            float* __restrict__ ego) {
    int warp = (blockIdx.x * blockDim.x + threadIdx.x) >> 5;
    int lane = threadIdx.x & 31;
    if (warp >= U_NUM) return;
    int d0 = lane * 2;
    float s0 = gu[d0]     + gu[D + d0]     + gu[2 * D + d0];
    float s1 = gu[d0 + 1] + gu[D + d0 + 1] + gu[2 * D + d0 + 1];
    float2 v = ((const float2*)(user_fea + (size_t)warp * D))[lane];
    v.x += s0; v.y += s1;
    ((float2*)(ego + (size_t)warp * D))[lane] = v;
}

// ---------------- item ego init: ego = tanh(item_fea @ W^T + b) + sum(g_emb_i, 0)
// 128 threads, 128x64 tile, 8x8 per thread, f32x2 FMAs, reg-prefetch pipeline.
#define BM 128
#define BK 16

__global__ __launch_bounds__(128) void k_item_gemm(
    const float* __restrict__ A,     // [I_NUM, F_DIM]
    const float* __restrict__ W,     // [D, F_DIM]
    const float* __restrict__ bias,  // [D]
    const float* __restrict__ gi,    // [3, D]
    float* __restrict__ ego) {
    __shared__ float As[BK][BM + 4];   // [k][row]
    __shared__ float Bs[BK][D + 4];    // [k][n]
    int t = threadIdx.x;
    int tx = t & 7;        // col group: cols tx*8 .. +7
    int ty = t >> 3;       // row group: rows ty*8 .. +7
    int r0 = blockIdx.x * BM;

    // A tile 128x16: per thread 4x float4 (aligned: k offset multiple of 4)
    int la_r = t >> 2;             // 0..31 (+32*s)
    int la_k = (t & 3) * 4;        // 0,4,8,12
    // B tile 64(n) x 16(k): per thread 2x float4 along k (aligned)
    int lb_n  = t & 63;            // 0..63
    int lb_k4 = (t >> 6) * 4;      // 0 or 4; +8 per stage covers k 0..15

    unsigned long long acc2[8][4];
    #pragma unroll
    for (int i = 0; i < 8; i++)
        #pragma unroll
        for (int j = 0; j < 4; j++) acc2[i][j] = 0ull;

    float4 pa[4], pb[2];
    #pragma unroll
    for (int s = 0; s < 4; s++) {
        int gr = r0 + la_r + s * 32;
        pa[s] = (gr < I_NUM) ? *(const float4*)(A + (size_t)gr * F_DIM + la_k)
                             : make_float4(0.f, 0.f, 0.f, 0.f);
    }
    #pragma unroll
    for (int s = 0; s < 2; s++)
        pb[s] = *(const float4*)(W + (size_t)lb_n * F_DIM + lb_k4 + s * 8);

    for (int k0 = 0; k0 < F_DIM; k0 += BK) {
        #pragma unroll
        for (int s = 0; s < 4; s++) {
            int row = la_r + s * 32;
            As[la_k][row]     = pa[s].x;
            As[la_k + 1][row] = pa[s].y;
            As[la_k + 2][row] = pa[s].z;
            As[la_k + 3][row] = pa[s].w;
        }
        #pragma unroll
        for (int s = 0; s < 2; s++) {
            int k = lb_k4 + s * 8;
            Bs[k][lb_n]     = pb[s].x;
            Bs[k + 1][lb_n] = pb[s].y;
            Bs[k + 2][lb_n] = pb[s].z;
            Bs[k + 3][lb_n] = pb[s].w;
        }
        __syncthreads();

        if (k0 + BK < F_DIM) {
            #pragma unroll
            for (int s = 0; s < 4; s++) {
                int gr = r0 + la_r + s * 32;
                pa[s] = (gr < I_NUM)
                      ? *(const float4*)(A + (size_t)gr * F_DIM + k0 + BK + la_k)
                      : make_float4(0.f, 0.f, 0.f, 0.f);
            }
            #pragma unroll
            for (int s = 0; s < 2; s++)
                pb[s] = *(const float4*)(W + (size_t)lb_n * F_DIM + k0 + BK + lb_k4 + s * 8);
        }

        #pragma unroll
        for (int kk = 0; kk < BK; kk++) {
            float4 a0 = *(const float4*)&As[kk][ty * 8];
            float4 a1 = *(const float4*)&As[kk][ty * 8 + 4];
            float4 b0 = *(const float4*)&Bs[kk][tx * 8];
            float4 b1 = *(const float4*)&Bs[kk][tx * 8 + 4];
            unsigned long long bb[4] = { pack2(b0.x, b0.y), pack2(b0.z, b0.w),
                                         pack2(b1.x, b1.y), pack2(b1.z, b1.w) };
            float av[8] = { a0.x, a0.y, a0.z, a0.w, a1.x, a1.y, a1.z, a1.w };
            #pragma unroll
            for (int i = 0; i < 8; i++) {
                unsigned long long a2 = pack2(av[i], av[i]);
                #pragma unroll
                for (int j = 0; j < 4; j++) fma2(acc2[i][j], a2, bb[j]);
            }
        }
        __syncthreads();
    }

    #pragma unroll
    for (int j = 0; j < 4; j++) {
        int n = tx * 8 + 2 * j;
        float bn0 = bias[n],     sn0 = gi[n]     + gi[D + n]     + gi[2 * D + n];
        float bn1 = bias[n + 1], sn1 = gi[n + 1] + gi[D + n + 1] + gi[2 * D + n + 1];
        #pragma unroll
        for (int i = 0; i < 8; i++) {
            int r = r0 + ty * 8 + i;
            if (r < I_NUM) {
                float c0, c1;
                unpack2(acc2[i][j], c0, c1);
                size_t off = (size_t)(U_NUM + r) * D + n;
                ego[off]     = tanhf(c0 + bn0) + sn0;
                ego[off + 1] = tanhf(c1 + bn1) + sn1;
            }
        }
    }
}

// ---------------- layer core: y_row = w * (A x)_row   (half-warp per row)
template <bool FINAL>
__global__ __launch_bounds__(256) void k_layer_t(
    const float* __restrict__ x, float* __restrict__ y,
    const int* __restrict__ cnt, const int2* __restrict__ elle,
    const float* __restrict__ ego,
    const float* __restrict__ y0, const float* __restrict__ y1,
    const float* __restrict__ y2) {
    int warp = (blockIdx.x * blockDim.x + threadIdx.x) >> 5;
    int lane = threadIdx.x & 31;
    int half = lane >> 4;
    int hl   = lane & 15;
    int row  = warp * 2 + half;
    if (row >= N_NUM) return;

    int c = min(__ldg(cnt + row), ELL_W);
    const int2* ep = elle + (size_t)row * ELL_W;
    float4 acc = make_float4(0.f, 0.f, 0.f, 0.f);

    int e = 0;
    for (; e + 4 <= c; e += 4) {
        int2 e0 = __ldg(ep + e);
        int2 e1 = __ldg(ep + e + 1);
        int2 e2 = __ldg(ep + e + 2);
        int2 e3 = __ldg(ep + e + 3);
        float4 x0 = __ldg((const float4*)(x + (size_t)e0.x * D) + hl);
        float4 x1 = __ldg((const float4*)(x + (size_t)e1.x * D) + hl);
        float4 x2 = __ldg((const float4*)(x + (size_t)e2.x * D) + hl);
        float4 x3 = __ldg((const float4*)(x + (size_t)e3.x * D) + hl);
        float v0 = __int_as_float(e0.y), v1 = __int_as_float(e1.y);
        float v2 = __int_as_float(e2.y), v3 = __int_as_float(e3.y);
        acc.x = fmaf(v0, x0.x, acc.x); acc.y = fmaf(v0, x0.y, acc.y);
        acc.z = fmaf(v0, x0.z, acc.z); acc.w = fmaf(v0, x0.w, acc.w);
        acc.x = fmaf(v1, x1.x, acc.x); acc.y = fmaf(v1, x1.y, acc.y);
        acc.z = fmaf(v1, x1.z, acc.z); acc.w = fmaf(v1, x1.w, acc.w);
        acc.x = fmaf(v2, x2.x, acc.x); acc.y = fmaf(v2, x2.y, acc.y);
        acc.z = fmaf(v2, x2.z, acc.z); acc.w = fmaf(v2, x2.w, acc.w);
        acc.x = fmaf(v3, x3.x, acc.x); acc.y = fmaf(v3, x3.y, acc.y);
        acc.z = fmaf(v3, x3.z, acc.z); acc.w = fmaf(v3, x3.w, acc.w);
    }
    for (; e < c; e++) {
        int2 ee = __ldg(ep + e);
        float vv = __int_as_float(ee.y);
        float4 xv = __ldg((const float4*)(x + (size_t)ee.x * D) + hl);
        acc.x = fmaf(vv, xv.x, acc.x); acc.y = fmaf(vv, xv.y, acc.y);
        acc.z = fmaf(vv, xv.z, acc.z); acc.w = fmaf(vv, xv.w, acc.w);
    }

    size_t base = (size_t)row * D;
    float4 ev = __ldg((const float4*)(ego + base) + hl);
    float dot = acc.x * ev.x + acc.y * ev.y + acc.z * ev.z + acc.w * ev.w;
    float ssy = acc.x * acc.x + acc.y * acc.y + acc.z * acc.z + acc.w * acc.w;
    float sse = ev.x * ev.x + ev.y * ev.y + ev.z * ev.z + ev.w * ev.w;
    #pragma unroll
    for (int o = 8; o; o >>= 1) {
        dot += __shfl_xor_sync(0xffffffffu, dot, o);
        ssy += __shfl_xor_sync(0xffffffffu, ssy, o);
        sse += __shfl_xor_sync(0xffffffffu, sse, o);
    }
    float w = dot / (fmaxf(sqrtf(ssy), EPS) * fmaxf(sqrtf(sse), EPS));
    acc.x *= w; acc.y *= w; acc.z *= w; acc.w *= w;

    if (FINAL) {
        float4 a = __ldg((const float4*)(y0 + base) + hl);
        float4 b = __ldg((const float4*)(y1 + base) + hl);
        float4 cc = __ldg((const float4*)(y2 + base) + hl);
        acc.x += ev.x + a.x + b.x + cc.x;
        acc.y += ev.y + a.y + b.y + cc.y;
        acc.z += ev.z + a.z + b.z + cc.z;
        acc.w += ev.w + a.w + b.w + cc.w;
    }
    ((float4*)(y + base))[hl] = acc;
}

extern "C" void kernel_launch(void* const* d_in, const int* in_sizes, int n_in,
                              void* d_out, int out_size) {
    const int*   adj_row  = (const int*)d_in[0];
    const int*   adj_col  = (const int*)d_in[1];
    const float* adj_val  = (const float*)d_in[2];
    const float* user_fea = (const float*)d_in[3];
    const float* item_fea = (const float*)d_in[4];
    const float* g_emb_u  = (const float*)d_in[5];
    const float* g_emb_i  = (const float*)d_in[6];
    const float* mlp_w    = (const float*)d_in[7];
    const float* mlp_b    = (const float*)d_in[8];
    float* acc = (float*)d_out;

    float *ego_p, *b0, *b1, *b2;
    int *cnt_p; int2 *elle_p;
    cudaGetSymbolAddress((void**)&ego_p,  g_ego);
    cudaGetSymbolAddress((void**)&b0,     g_buf0);
    cudaGetSymbolAddress((void**)&b1,     g_buf1);
    cudaGetSymbolAddress((void**)&b2,     g_buf2);
    cudaGetSymbolAddress((void**)&cnt_p,  g_cnt);
    cudaGetSymbolAddress((void**)&elle_p, g_elle);

    cudaMemsetAsync(cnt_p, 0, N_NUM * sizeof(int));
    k_build<<<(E_NUM + 255) / 256, 256>>>(adj_row, adj_col, adj_val, cnt_p, elle_p);

    k_init_user<<<(U_NUM + 7) / 8, 256>>>(user_fea, g_emb_u, ego_p);
    k_item_gemm<<<(I_NUM + BM - 1) / BM, 128>>>(item_fea, mlp_w, mlp_b, g_emb_i, ego_p);

    int lgrid = (N_NUM / 2 + 7) / 8;
    k_layer_t<false><<<lgrid, 256>>>(ego_p, b0, cnt_p, elle_p, ego_p, b0, b1, b2);
    k_layer_t<false><<<lgrid, 256>>>(b0,    b1, cnt_p, elle_p, ego_p, b0, b1, b2);
    k_layer_t<false><<<lgrid, 256>>>(b1,    b2, cnt_p, elle_p, ego_p, b0, b1, b2);
    k_layer_t<true><<<lgrid, 256>>>(b2,    acc, cnt_p, elle_p, ego_p, b0, b1, b2);
}

// round 6
// speedup vs baseline: 2.1879x; 1.1518x over previous
#include <cuda_runtime.h>
#include <math.h>

#define U_NUM 100000
#define I_NUM 50000
#define N_NUM 150000
#define E_NUM 1200000
#define D 64
#define F_DIM 384
#define EPS 1e-8f
#define ELL_W 64

// Scratch (allocation-free rule: __device__ globals; zero-initialized at load)
__device__ float g_ego[(size_t)N_NUM * D];
__device__ float g_buf0[(size_t)N_NUM * D];
__device__ float g_buf1[(size_t)N_NUM * D];
__device__ float g_buf2[(size_t)N_NUM * D];
__device__ int   g_cnt[N_NUM];
__device__ int2  g_elle[(size_t)N_NUM * ELL_W];   // packed (col, val-bits); tail slots stay 0

// ---------------- helpers
__device__ __forceinline__ unsigned long long pack2(float lo, float hi) {
    unsigned long long r;
    asm("mov.b64 %0, {%1,%2};" : "=l"(r) : "f"(lo), "f"(hi));
    return r;
}
__device__ __forceinline__ void unpack2(unsigned long long p, float& lo, float& hi) {
    asm("mov.b64 {%0,%1}, %2;" : "=f"(lo), "=f"(hi) : "l"(p));
}
__device__ __forceinline__ void fma2(unsigned long long& d,
                                     unsigned long long a, unsigned long long b) {
    asm("fma.rn.f32x2 %0, %1, %2, %3;" : "=l"(d) : "l"(a), "l"(b), "l"(d));
}
__device__ __forceinline__ float tanh_fast(float x) {
    float r;
    asm("tanh.approx.f32 %0, %1;" : "=f"(r) : "f"(x));
    return r;
}

// ---------------- ELL build (packed col+val)
__global__ __launch_bounds__(256) void k_build(
    const int* __restrict__ rows, const int* __restrict__ cols,
    const float* __restrict__ vals,
    int* __restrict__ cnt, int2* __restrict__ elle) {
    int e = blockIdx.x * blockDim.x + threadIdx.x;
    if (e >= E_NUM) return;
    int r = __ldg(rows + e);
    int slot = atomicAdd(cnt + r, 1);
    if (slot < ELL_W) {
        int2 p;
        p.x = __ldg(cols + e);
        p.y = __float_as_int(__ldg(vals + e));
        elle[(size_t)r * ELL_W + slot] = p;
    }
}

// ---------------- user ego init: ego = user_fea + sum(g_emb_u, 0)
__global__ void k_init_user(const float* __restrict__ user_fea,
                            const float* __restrict__ gu,
                            float* __restrict__ ego) {
    int warp = (blockIdx.x * blockDim.x + threadIdx.x) >> 5;
    int lane = threadIdx.x & 31;
    if (warp >= U_NUM) return;
    int d0 = lane * 2;
    float s0 = gu[d0]     + gu[D + d0]     + gu[2 * D + d0];
    float s1 = gu[d0 + 1] + gu[D + d0 + 1] + gu[2 * D + d0 + 1];
    float2 v = ((const float2*)(user_fea + (size_t)warp * D))[lane];
    v.x += s0; v.y += s1;
    ((float2*)(ego + (size_t)warp * D))[lane] = v;
}

// ---------------- item ego init: ego = tanh(item_fea @ W^T + b) + sum(g_emb_i, 0)
#define BM 128
#define BK 16

__global__ __launch_bounds__(128) void k_item_gemm(
    const float* __restrict__ A,     // [I_NUM, F_DIM]
    const float* __restrict__ W,     // [D, F_DIM]
    const float* __restrict__ bias,  // [D]
    const float* __restrict__ gi,    // [3, D]
    float* __restrict__ ego) {
    __shared__ float As[BK][BM + 4];   // [k][row]
    __shared__ float Bs[BK][D + 4];    // [k][n]
    int t = threadIdx.x;
    int tx = t & 7;
    int ty = t >> 3;
    int r0 = blockIdx.x * BM;

    int la_r = t >> 2;
    int la_k = (t & 3) * 4;
    int lb_n  = t & 63;
    int lb_k4 = (t >> 6) * 4;

    unsigned long long acc2[8][4];
    #pragma unroll
    for (int i = 0; i < 8; i++)
        #pragma unroll
        for (int j = 0; j < 4; j++) acc2[i][j] = 0ull;

    float4 pa[4], pb[2];
    #pragma unroll
    for (int s = 0; s < 4; s++) {
        int gr = r0 + la_r + s * 32;
        pa[s] = (gr < I_NUM) ? *(const float4*)(A + (size_t)gr * F_DIM + la_k)
                             : make_float4(0.f, 0.f, 0.f, 0.f);
    }
    #pragma unroll
    for (int s = 0; s < 2; s++)
        pb[s] = *(const float4*)(W + (size_t)lb_n * F_DIM + lb_k4 + s * 8);

    for (int k0 = 0; k0 < F_DIM; k0 += BK) {
        #pragma unroll
        for (int s = 0; s < 4; s++) {
            int row = la_r + s * 32;
            As[la_k][row]     = pa[s].x;
            As[la_k + 1][row] = pa[s].y;
            As[la_k + 2][row] = pa[s].z;
            As[la_k + 3][row] = pa[s].w;
        }
        #pragma unroll
        for (int s = 0; s < 2; s++) {
            int k = lb_k4 + s * 8;
            Bs[k][lb_n]     = pb[s].x;
            Bs[k + 1][lb_n] = pb[s].y;
            Bs[k + 2][lb_n] = pb[s].z;
            Bs[k + 3][lb_n] = pb[s].w;
        }
        __syncthreads();

        if (k0 + BK < F_DIM) {
            #pragma unroll
            for (int s = 0; s < 4; s++) {
                int gr = r0 + la_r + s * 32;
                pa[s] = (gr < I_NUM)
                      ? *(const float4*)(A + (size_t)gr * F_DIM + k0 + BK + la_k)
                      : make_float4(0.f, 0.f, 0.f, 0.f);
            }
            #pragma unroll
            for (int s = 0; s < 2; s++)
                pb[s] = *(const float4*)(W + (size_t)lb_n * F_DIM + k0 + BK + lb_k4 + s * 8);
        }

        #pragma unroll
        for (int kk = 0; kk < BK; kk++) {
            float4 a0 = *(const float4*)&As[kk][ty * 8];
            float4 a1 = *(const float4*)&As[kk][ty * 8 + 4];
            float4 b0 = *(const float4*)&Bs[kk][tx * 8];
            float4 b1 = *(const float4*)&Bs[kk][tx * 8 + 4];
            unsigned long long bb[4] = { pack2(b0.x, b0.y), pack2(b0.z, b0.w),
                                         pack2(b1.x, b1.y), pack2(b1.z, b1.w) };
            float av[8] = { a0.x, a0.y, a0.z, a0.w, a1.x, a1.y, a1.z, a1.w };
            #pragma unroll
            for (int i = 0; i < 8; i++) {
                unsigned long long a2 = pack2(av[i], av[i]);
                #pragma unroll
                for (int j = 0; j < 4; j++) fma2(acc2[i][j], a2, bb[j]);
            }
        }
        __syncthreads();
    }

    #pragma unroll
    for (int j = 0; j < 4; j++) {
        int n = tx * 8 + 2 * j;
        float bn0 = bias[n],     sn0 = gi[n]     + gi[D + n]     + gi[2 * D + n];
        float bn1 = bias[n + 1], sn1 = gi[n + 1] + gi[D + n + 1] + gi[2 * D + n + 1];
        #pragma unroll
        for (int i = 0; i < 8; i++) {
            int r = r0 + ty * 8 + i;
            if (r < I_NUM) {
                float c0, c1;
                unpack2(acc2[i][j], c0, c1);
                size_t off = (size_t)(U_NUM + r) * D + n;
                ego[off]     = tanh_fast(c0 + bn0) + sn0;
                ego[off + 1] = tanh_fast(c1 + bn1) + sn1;
            }
        }
    }
}

// ---------------- layer core: y_row = w * (A x)_row  (half-warp per row)
// Edge slots beyond cnt are zero (col=0, val=0.0) -> contribute nothing, so we
// process a full 8-edge batch unconditionally: 4 independent int4 loads, then
// 8 gathers all in flight (one latency exposure per batch).
template <bool FINAL>
__global__ __launch_bounds__(256) void k_layer_t(
    const float* __restrict__ x, float* __restrict__ y,
    const int* __restrict__ cnt, const int2* __restrict__ elle,
    const float* __restrict__ ego,
    const float* __restrict__ y0, const float* __restrict__ y1,
    const float* __restrict__ y2) {
    int warp = (blockIdx.x * blockDim.x + threadIdx.x) >> 5;
    int lane = threadIdx.x & 31;
    int half = lane >> 4;
    int hl   = lane & 15;
    int row  = warp * 2 + half;
    if (row >= N_NUM) return;

    int c = min(__ldg(cnt + row), ELL_W);
    const int4* ep4 = (const int4*)(elle + (size_t)row * ELL_W);  // 2 edges / int4
    float4 acc = make_float4(0.f, 0.f, 0.f, 0.f);

    for (int b = 0; b < c; b += 8) {
        int q = b >> 1;
        int4 q0 = __ldg(ep4 + q);
        int4 q1 = __ldg(ep4 + q + 1);
        int4 q2 = __ldg(ep4 + q + 2);
        int4 q3 = __ldg(ep4 + q + 3);
        float4 x0 = __ldg((const float4*)(x + (size_t)q0.x * D) + hl);
        float4 x1 = __ldg((const float4*)(x + (size_t)q0.z * D) + hl);
        float4 x2 = __ldg((const float4*)(x + (size_t)q1.x * D) + hl);
        float4 x3 = __ldg((const float4*)(x + (size_t)q1.z * D) + hl);
        float4 x4 = __ldg((const float4*)(x + (size_t)q2.x * D) + hl);
        float4 x5 = __ldg((const float4*)(x + (size_t)q2.z * D) + hl);
        float4 x6 = __ldg((const float4*)(x + (size_t)q3.x * D) + hl);
        float4 x7 = __ldg((const float4*)(x + (size_t)q3.z * D) + hl);
        float v0 = __int_as_float(q0.y), v1 = __int_as_float(q0.w);
        float v2 = __int_as_float(q1.y), v3 = __int_as_float(q1.w);
        float v4 = __int_as_float(q2.y), v5 = __int_as_float(q2.w);
        float v6 = __int_as_float(q3.y), v7 = __int_as_float(q3.w);
        acc.x = fmaf(v0, x0.x, acc.x); acc.y = fmaf(v0, x0.y, acc.y);
        acc.z = fmaf(v0, x0.z, acc.z); acc.w = fmaf(v0, x0.w, acc.w);
        acc.x = fmaf(v1, x1.x, acc.x); acc.y = fmaf(v1, x1.y, acc.y);
        acc.z = fmaf(v1, x1.z, acc.z); acc.w = fmaf(v1, x1.w, acc.w);
        acc.x = fmaf(v2, x2.x, acc.x); acc.y = fmaf(v2, x2.y, acc.y);
        acc.z = fmaf(v2, x2.z, acc.z); acc.w = fmaf(v2, x2.w, acc.w);
        acc.x = fmaf(v3, x3.x, acc.x); acc.y = fmaf(v3, x3.y, acc.y);
        acc.z = fmaf(v3, x3.z, acc.z); acc.w = fmaf(v3, x3.w, acc.w);
        acc.x = fmaf(v4, x4.x, acc.x); acc.y = fmaf(v4, x4.y, acc.y);
        acc.z = fmaf(v4, x4.z, acc.z); acc.w = fmaf(v4, x4.w, acc.w);
        acc.x = fmaf(v5, x5.x, acc.x); acc.y = fmaf(v5, x5.y, acc.y);
        acc.z = fmaf(v5, x5.z, acc.z); acc.w = fmaf(v5, x5.w, acc.w);
        acc.x = fmaf(v6, x6.x, acc.x); acc.y = fmaf(v6, x6.y, acc.y);
        acc.z = fmaf(v6, x6.z, acc.z); acc.w = fmaf(v6, x6.w, acc.w);
        acc.x = fmaf(v7, x7.x, acc.x); acc.y = fmaf(v7, x7.y, acc.y);
        acc.z = fmaf(v7, x7.z, acc.z); acc.w = fmaf(v7, x7.w, acc.w);
    }

    size_t base = (size_t)row * D;
    float4 ev = __ldg((const float4*)(ego + base) + hl);
    float dot = acc.x * ev.x + acc.y * ev.y + acc.z * ev.z + acc.w * ev.w;
    float ssy = acc.x * acc.x + acc.y * acc.y + acc.z * acc.z + acc.w * acc.w;
    float sse = ev.x * ev.x + ev.y * ev.y + ev.z * ev.z + ev.w * ev.w;
    #pragma unroll
    for (int o = 8; o; o >>= 1) {
        dot += __shfl_xor_sync(0xffffffffu, dot, o);
        ssy += __shfl_xor_sync(0xffffffffu, ssy, o);
        sse += __shfl_xor_sync(0xffffffffu, sse, o);
    }
    float w = dot / (fmaxf(sqrtf(ssy), EPS) * fmaxf(sqrtf(sse), EPS));
    acc.x *= w; acc.y *= w; acc.z *= w; acc.w *= w;

    if (FINAL) {
        float4 a = __ldg((const float4*)(y0 + base) + hl);
        float4 b = __ldg((const float4*)(y1 + base) + hl);
        float4 cc = __ldg((const float4*)(y2 + base) + hl);
        acc.x += ev.x + a.x + b.x + cc.x;
        acc.y += ev.y + a.y + b.y + cc.y;
        acc.z += ev.z + a.z + b.z + cc.z;
        acc.w += ev.w + a.w + b.w + cc.w;
    }
    ((float4*)(y + base))[hl] = acc;
}

extern "C" void kernel_launch(void* const* d_in, const int* in_sizes, int n_in,
                              void* d_out, int out_size) {
    const int*   adj_row  = (const int*)d_in[0];
    const int*   adj_col  = (const int*)d_in[1];
    const float* adj_val  = (const float*)d_in[2];
    const float* user_fea = (const float*)d_in[3];
    const float* item_fea = (const float*)d_in[4];
    const float* g_emb_u  = (const float*)d_in[5];
    const float* g_emb_i  = (const float*)d_in[6];
    const float* mlp_w    = (const float*)d_in[7];
    const float* mlp_b    = (const float*)d_in[8];
    float* acc = (float*)d_out;

    float *ego_p, *b0, *b1, *b2;
    int *cnt_p; int2 *elle_p;
    cudaGetSymbolAddress((void**)&ego_p,  g_ego);
    cudaGetSymbolAddress((void**)&b0,     g_buf0);
    cudaGetSymbolAddress((void**)&b1,     g_buf1);
    cudaGetSymbolAddress((void**)&b2,     g_buf2);
    cudaGetSymbolAddress((void**)&cnt_p,  g_cnt);
    cudaGetSymbolAddress((void**)&elle_p, g_elle);

    cudaMemsetAsync(cnt_p, 0, N_NUM * sizeof(int));
    k_build<<<(E_NUM + 255) / 256, 256>>>(adj_row, adj_col, adj_val, cnt_p, elle_p);

    k_init_user<<<(U_NUM + 7) / 8, 256>>>(user_fea, g_emb_u, ego_p);
    k_item_gemm<<<(I_NUM + BM - 1) / BM, 128>>>(item_fea, mlp_w, mlp_b, g_emb_i, ego_p);

    int lgrid = (N_NUM / 2 + 7) / 8;
    k_layer_t<false><<<lgrid, 256>>>(ego_p, b0, cnt_p, elle_p, ego_p, b0, b1, b2);
    k_layer_t<false><<<lgrid, 256>>>(b0,    b1, cnt_p, elle_p, ego_p, b0, b1, b2);
    k_layer_t<false><<<lgrid, 256>>>(b1,    b2, cnt_p, elle_p, ego_p, b0, b1, b2);
    k_layer_t<true><<<lgrid, 256>>>(b2,    acc, cnt_p, elle_p, ego_p, b0, b1, b2);
}

// round 9
// speedup vs baseline: 2.4692x; 1.1286x over previous
#include <cuda_runtime.h>
#include <cuda_bf16.h>
#include <mma.h>
#include <math.h>

using namespace nvcuda;

#define U_NUM 100000
#define I_NUM 50000
#define N_NUM 150000
#define E_NUM 1200000
#define D 64
#define F_DIM 384
#define EPS 1e-8f
#define ELL_W 64

// Scratch (allocation-free rule: __device__ globals; zero-initialized at load)
__device__ float g_ego[(size_t)N_NUM * D];
__device__ float g_buf0[(size_t)N_NUM * D];
__device__ float g_buf1[(size_t)N_NUM * D];
__device__ float g_buf2[(size_t)N_NUM * D];
__device__ int   g_cnt[N_NUM];
__device__ int2  g_elle[(size_t)N_NUM * ELL_W];   // packed (col, val-bits); tail slots stay 0

__device__ __forceinline__ float tanh_fast(float x) {
    float r;
    asm("tanh.approx.f32 %0, %1;" : "=f"(r) : "f"(x));
    return r;
}

// ---------------- ELL build (packed col+val)
__global__ __launch_bounds__(256) void k_build(
    const int* __restrict__ rows, const int* __restrict__ cols,
    const float* __restrict__ vals,
    int* __restrict__ cnt, int2* __restrict__ elle) {
    int e = blockIdx.x * blockDim.x + threadIdx.x;
    if (e >= E_NUM) return;
    int r = __ldg(rows + e);
    int slot = atomicAdd(cnt + r, 1);
    if (slot < ELL_W) {
        int2 p;
        p.x = __ldg(cols + e);
        p.y = __float_as_int(__ldg(vals + e));
        elle[(size_t)r * ELL_W + slot] = p;
    }
}

// ---------------- user ego init: ego = user_fea + sum(g_emb_u, 0)
__global__ void k_init_user(const float* __restrict__ user_fea,
                            const float* __restrict__ gu,
                            float* __restrict__ ego) {
    int warp = (blockIdx.x * blockDim.x + threadIdx.x) >> 5;
    int lane = threadIdx.x & 31;
    if (warp >= U_NUM) return;
    int d0 = lane * 2;
    float s0 = gu[d0]     + gu[D + d0]     + gu[2 * D + d0];
    float s1 = gu[d0 + 1] + gu[D + d0 + 1] + gu[2 * D + d0 + 1];
    float2 v = ((const float2*)(user_fea + (size_t)warp * D))[lane];
    v.x += s0; v.y += s1;
    ((float2*)(ego + (size_t)warp * D))[lane] = v;
}

// ---------------- item ego init: ego = tanh(item_fea @ W^T + b) + sum(g_emb_i, 0)
// 3-term bf16-split WMMA (Markidis): A*W ~= Ah*Wh + Ah*Wl + Al*Wh, fp32 acc.
#define BM 128
#define GK 32
#define LDA 40   // bf16 elems; 80B row stride (16B multiple)
#define LDW 40

#define SM_AS_HI 0
#define SM_AS_LO (SM_AS_HI + BM * LDA * 2)            // 10240
#define SM_WS_HI (SM_AS_LO + BM * LDA * 2)            // 20480
#define SM_WS_LO (SM_WS_HI + D * LDW * 2)             // 25600
#define SM_MAIN  (SM_WS_LO + D * LDW * 2)             // 30720
#define SM_OS_SZ (8 * 16 * D * 4)                     // 32768
#define SM_TOTAL (SM_OS_SZ > SM_MAIN ? SM_OS_SZ : SM_MAIN)

__device__ __forceinline__ void split_store(__nv_bfloat16* hi, __nv_bfloat16* lo, float v) {
    __nv_bfloat16 h = __float2bfloat16(v);
    *hi = h;
    *lo = __float2bfloat16(v - __bfloat162float(h));
}

__global__ __launch_bounds__(256) void k_item_gemm(
    const float* __restrict__ A,     // [I_NUM, F_DIM] fp32
    const float* __restrict__ W,     // [D, F_DIM] fp32
    const float* __restrict__ bias,  // [D]
    const float* __restrict__ gi,    // [3, D]
    float* __restrict__ ego) {
    __shared__ __align__(16) char smem[SM_TOTAL];
    __nv_bfloat16 (*AsH)[LDA] = (__nv_bfloat16(*)[LDA])(smem + SM_AS_HI);
    __nv_bfloat16 (*AsL)[LDA] = (__nv_bfloat16(*)[LDA])(smem + SM_AS_LO);
    __nv_bfloat16 (*WsH)[LDW] = (__nv_bfloat16(*)[LDW])(smem + SM_WS_HI);
    __nv_bfloat16 (*WsL)[LDW] = (__nv_bfloat16(*)[LDW])(smem + SM_WS_LO);

    int t = threadIdx.x;
    int w = t >> 5;
    int lane = t & 31;
    int r0 = blockIdx.x * BM;

    wmma::fragment<wmma::accumulator, 16, 16, 16, float> cfrag[4];
    #pragma unroll
    for (int nf = 0; nf < 4; nf++) wmma::fill_fragment(cfrag[nf], 0.0f);

    int ar = t >> 1;          // A row, cols (t&1)*16..+15
    int ac = (t & 1) * 16;
    int wr = t >> 2;          // W row, cols (t&3)*8..+7
    int wc = (t & 3) * 8;

    for (int k0 = 0; k0 < F_DIM; k0 += GK) {
        {
            int gr = r0 + ar;
            if (gr < I_NUM) {
                const float4* src = (const float4*)(A + (size_t)gr * F_DIM + k0 + ac);
                #pragma unroll
                for (int s = 0; s < 4; s++) {
                    float4 v = __ldg(src + s);
                    split_store(&AsH[ar][ac + s * 4],     &AsL[ar][ac + s * 4],     v.x);
                    split_store(&AsH[ar][ac + s * 4 + 1], &AsL[ar][ac + s * 4 + 1], v.y);
                    split_store(&AsH[ar][ac + s * 4 + 2], &AsL[ar][ac + s * 4 + 2], v.z);
                    split_store(&AsH[ar][ac + s * 4 + 3], &AsL[ar][ac + s * 4 + 3], v.w);
                }
            } else {
                #pragma unroll
                for (int s = 0; s < 16; s++) {
                    AsH[ar][ac + s] = __float2bfloat16(0.f);
                    AsL[ar][ac + s] = __float2bfloat16(0.f);
                }
            }
        }
        {
            const float4* src = (const float4*)(W + (size_t)wr * F_DIM + k0 + wc);
            #pragma unroll
            for (int s = 0; s < 2; s++) {
                float4 v = __ldg(src + s);
                split_store(&WsH[wr][wc + s * 4],     &WsL[wr][wc + s * 4],     v.x);
                split_store(&WsH[wr][wc + s * 4 + 1], &WsL[wr][wc + s * 4 + 1], v.y);
                split_store(&WsH[wr][wc + s * 4 + 2], &WsL[wr][wc + s * 4 + 2], v.z);
                split_store(&WsH[wr][wc + s * 4 + 3], &WsL[wr][wc + s * 4 + 3], v.w);
            }
        }
        __syncthreads();

        #pragma unroll
        for (int kk = 0; kk < GK; kk += 16) {
            wmma::fragment<wmma::matrix_a, 16, 16, 16, __nv_bfloat16, wmma::row_major> aH, aL;
            wmma::load_matrix_sync(aH, &AsH[w * 16][kk], LDA);
            wmma::load_matrix_sync(aL, &AsL[w * 16][kk], LDA);
            #pragma unroll
            for (int nf = 0; nf < 4; nf++) {
                wmma::fragment<wmma::matrix_b, 16, 16, 16, __nv_bfloat16, wmma::col_major> bH, bL;
                wmma::load_matrix_sync(bH, &WsH[nf * 16][kk], LDW);
                wmma::load_matrix_sync(bL, &WsL[nf * 16][kk], LDW);
                wmma::mma_sync(cfrag[nf], aH, bH, cfrag[nf]);
                wmma::mma_sync(cfrag[nf], aH, bL, cfrag[nf]);
                wmma::mma_sync(cfrag[nf], aL, bH, cfrag[nf]);
            }
        }
        __syncthreads();
    }

    // epilogue: reuse smem as Os[8][16][D]
    float (*Os)[16][D] = (float(*)[16][D])smem;
    #pragma unroll
    for (int nf = 0; nf < 4; nf++)
        wmma::store_matrix_sync(&Os[w][0][nf * 16], cfrag[nf], D, wmma::mem_row_major);
    __syncwarp();

    for (int idx = lane; idx < 16 * D; idx += 32) {
        int i = idx >> 6;
        int n = idx & 63;
        int r = r0 + w * 16 + i;
        if (r < I_NUM) {
            float c = Os[w][i][n];
            float sn = gi[n] + gi[D + n] + gi[2 * D + n];
            ego[(size_t)(U_NUM + r) * D + n] = tanh_fast(c + bias[n]) + sn;
        }
    }
}

// ---------------- layer core: y_row = w * (A x)_row  (half-warp per row)
template <bool FINAL>
__global__ __launch_bounds__(256) void k_layer_t(
    const float* __restrict__ x, float* __restrict__ y,
    const int* __restrict__ cnt, const int2* __restrict__ elle,
    const float* __restrict__ ego,
    const float* __restrict__ y0, const float* __restrict__ y1,
    const float* __restrict__ y2) {
    int warp = (blockIdx.x * blockDim.x + threadIdx.x) >> 5;
    int lane = threadIdx.x & 31;
    int half = lane >> 4;
    int hl   = lane & 15;
    int row  = warp * 2 + half;
    if (row >= N_NUM) return;

    int c = min(__ldg(cnt + row), ELL_W);
    const int4* ep4 = (const int4*)(elle + (size_t)row * ELL_W);
    float4 acc = make_float4(0.f, 0.f, 0.f, 0.f);

    for (int b = 0; b < c; b += 8) {
        int q = b >> 1;
        int4 q0 = __ldg(ep4 + q);
        int4 q1 = __ldg(ep4 + q + 1);
        int4 q2 = __ldg(ep4 + q + 2);
        int4 q3 = __ldg(ep4 + q + 3);
        float4 x0 = __ldg((const float4*)(x + (size_t)q0.x * D) + hl);
        float4 x1 = __ldg((const float4*)(x + (size_t)q0.z * D) + hl);
        float4 x2 = __ldg((const float4*)(x + (size_t)q1.x * D) + hl);
        float4 x3 = __ldg((const float4*)(x + (size_t)q1.z * D) + hl);
        float4 x4 = __ldg((const float4*)(x + (size_t)q2.x * D) + hl);
        float4 x5 = __ldg((const float4*)(x + (size_t)q2.z * D) + hl);
        float4 x6 = __ldg((const float4*)(x + (size_t)q3.x * D) + hl);
        float4 x7 = __ldg((const float4*)(x + (size_t)q3.z * D) + hl);
        float v0 = __int_as_float(q0.y), v1 = __int_as_float(q0.w);
        float v2 = __int_as_float(q1.y), v3 = __int_as_float(q1.w);
        float v4 = __int_as_float(q2.y), v5 = __int_as_float(q2.w);
        float v6 = __int_as_float(q3.y), v7 = __int_as_float(q3.w);
        acc.x = fmaf(v0, x0.x, acc.x); acc.y = fmaf(v0, x0.y, acc.y);
        acc.z = fmaf(v0, x0.z, acc.z); acc.w = fmaf(v0, x0.w, acc.w);
        acc.x = fmaf(v1, x1.x, acc.x); acc.y = fmaf(v1, x1.y, acc.y);
        acc.z = fmaf(v1, x1.z, acc.z); acc.w = fmaf(v1, x1.w, acc.w);
        acc.x = fmaf(v2, x2.x, acc.x); acc.y = fmaf(v2, x2.y, acc.y);
        acc.z = fmaf(v2, x2.z, acc.z); acc.w = fmaf(v2, x2.w, acc.w);
        acc.x = fmaf(v3, x3.x, acc.x); acc.y = fmaf(v3, x3.y, acc.y);
        acc.z = fmaf(v3, x3.z, acc.z); acc.w = fmaf(v3, x3.w, acc.w);
        acc.x = fmaf(v4, x4.x, acc.x); acc.y = fmaf(v4, x4.y, acc.y);
        acc.z = fmaf(v4, x4.z, acc.z); acc.w = fmaf(v4, x4.w, acc.w);
        acc.x = fmaf(v5, x5.x, acc.x); acc.y = fmaf(v5, x5.y, acc.y);
        acc.z = fmaf(v5, x5.z, acc.z); acc.w = fmaf(v5, x5.w, acc.w);
        acc.x = fmaf(v6, x6.x, acc.x); acc.y = fmaf(v6, x6.y, acc.y);
        acc.z = fmaf(v6, x6.z, acc.z); acc.w = fmaf(v6, x6.w, acc.w);
        acc.x = fmaf(v7, x7.x, acc.x); acc.y = fmaf(v7, x7.y, acc.y);
        acc.z = fmaf(v7, x7.z, acc.z); acc.w = fmaf(v7, x7.w, acc.w);
    }

    size_t base = (size_t)row * D;
    float4 ev = __ldg((const float4*)(ego + base) + hl);
    float dot = acc.x * ev.x + acc.y * ev.y + acc.z * ev.z + acc.w * ev.w;
    float ssy = acc.x * acc.x + acc.y * acc.y + acc.z * acc.z + acc.w * acc.w;
    float sse = ev.x * ev.x + ev.y * ev.y + ev.z * ev.z + ev.w * ev.w;
    #pragma unroll
    for (int o = 8; o; o >>= 1) {
        dot += __shfl_xor_sync(0xffffffffu, dot, o);
        ssy += __shfl_xor_sync(0xffffffffu, ssy, o);
        sse += __shfl_xor_sync(0xffffffffu, sse, o);
    }
    float w = dot / (fmaxf(sqrtf(ssy), EPS) * fmaxf(sqrtf(sse), EPS));
    acc.x *= w; acc.y *= w; acc.z *= w; acc.w *= w;

    if (FINAL) {
        float4 a = __ldg((const float4*)(y0 + base) + hl);
        float4 b = __ldg((const float4*)(y1 + base) + hl);
        float4 cc = __ldg((const float4*)(y2 + base) + hl);
        acc.x += ev.x + a.x + b.x + cc.x;
        acc.y += ev.y + a.y + b.y + cc.y;
        acc.z += ev.z + a.z + b.z + cc.z;
        acc.w += ev.w + a.w + b.w + cc.w;
    }
    ((float4*)(y + base))[hl] = acc;
}

extern "C" void kernel_launch(void* const* d_in, const int* in_sizes, int n_in,
                              void* d_out, int out_size) {
    const int*   adj_row  = (const int*)d_in[0];
    const int*   adj_col  = (const int*)d_in[1];
    const float* adj_val  = (const float*)d_in[2];
    const float* user_fea = (const float*)d_in[3];
    const float* item_fea = (const float*)d_in[4];
    const float* g_emb_u  = (const float*)d_in[5];
    const float* g_emb_i  = (const float*)d_in[6];
    const float* mlp_w    = (const float*)d_in[7];
    const float* mlp_b    = (const float*)d_in[8];
    float* acc = (float*)d_out;

    float *ego_p, *b0, *b1, *b2;
    int *cnt_p; int2 *elle_p;
    cudaGetSymbolAddress((void**)&ego_p,  g_ego);
    cudaGetSymbolAddress((void**)&b0,     g_buf0);
    cudaGetSymbolAddress((void**)&b1,     g_buf1);
    cudaGetSymbolAddress((void**)&b2,     g_buf2);
    cudaGetSymbolAddress((void**)&cnt_p,  g_cnt);
    cudaGetSymbolAddress((void**)&elle_p, g_elle);

    cudaMemsetAsync(cnt_p, 0, N_NUM * sizeof(int));
    k_build<<<(E_NUM + 255) / 256, 256>>>(adj_row, adj_col, adj_val, cnt_p, elle_p);

    k_init_user<<<(U_NUM + 7) / 8, 256>>>(user_fea, g_emb_u, ego_p);
    k_item_gemm<<<(I_NUM + BM - 1) / BM, 256>>>(item_fea, mlp_w, mlp_b, g_emb_i, ego_p);

    int lgrid = (N_NUM / 2 + 7) / 8;
    k_layer_t<false><<<lgrid, 256>>>(ego_p, b0, cnt_p, elle_p, ego_p, b0, b1, b2);
    k_layer_t<false><<<lgrid, 256>>>(b0,    b1, cnt_p, elle_p, ego_p, b0, b1, b2);
    k_layer_t<false><<<lgrid, 256>>>(b1,    b2, cnt_p, elle_p, ego_p, b0, b1, b2);
    k_layer_t<true><<<lgrid, 256>>>(b2,    acc, cnt_p, elle_p, ego_p, b0, b1, b2);
}

// round 10
// speedup vs baseline: 2.6011x; 1.0534x over previous
#include <cuda_runtime.h>
#include <cuda_bf16.h>
#include <mma.h>
#include <math.h>

using namespace nvcuda;

#define U_NUM 100000
#define I_NUM 50000
#define N_NUM 150000
#define E_NUM 1200000
#define D 64
#define F_DIM 384
#define EPS 1e-8f
#define ELL_W 64

// Scratch (allocation-free rule: __device__ globals; zero-initialized at load)
__device__ float g_ego[(size_t)N_NUM * D];
__device__ float g_buf0[(size_t)N_NUM * D];
__device__ float g_buf1[(size_t)N_NUM * D];
__device__ float g_buf2[(size_t)N_NUM * D];
__device__ int   g_cnt[N_NUM];
__device__ int2  g_elle[(size_t)N_NUM * ELL_W];   // packed (col, val-bits); tail slots stay 0

__device__ __forceinline__ float tanh_fast(float x) {
    float r;
    asm("tanh.approx.f32 %0, %1;" : "=f"(r) : "f"(x));
    return r;
}

// ---------------- fused preamble: [gemm tiles | ELL build | user init], one kernel
#define BM 128
#define GK 32
#define LDA 40
#define LDW 40

#define GEMM_BLOCKS ((I_NUM + BM - 1) / BM)   // 391
#define BUILD_BLOCKS 320
#define USER_BLOCKS  320
#define PRE_BLOCKS (GEMM_BLOCKS + BUILD_BLOCKS + USER_BLOCKS)

#define SM_AS_HI 0
#define SM_AS_LO (SM_AS_HI + BM * LDA * 2)            // 10240
#define SM_WS_HI (SM_AS_LO + BM * LDA * 2)            // 20480
#define SM_WS_LO (SM_WS_HI + D * LDW * 2)             // 25600
#define SM_MAIN  (SM_WS_LO + D * LDW * 2)             // 30720
#define SM_OS_SZ (8 * 16 * D * 4)                     // 32768
#define SM_TOTAL (SM_OS_SZ > SM_MAIN ? SM_OS_SZ : SM_MAIN)

__device__ __forceinline__ void split_store(__nv_bfloat16* hi, __nv_bfloat16* lo, float v) {
    __nv_bfloat16 h = __float2bfloat16(v);
    *hi = h;
    *lo = __float2bfloat16(v - __bfloat162float(h));
}

__global__ __launch_bounds__(256) void k_preamble(
    const float* __restrict__ A,     // item_fea [I_NUM, F_DIM]
    const float* __restrict__ W,     // mlp_w [D, F_DIM]
    const float* __restrict__ bias,
    const float* __restrict__ gi,
    const int* __restrict__ rows, const int* __restrict__ cols,
    const float* __restrict__ vals,
    const float* __restrict__ user_fea,
    const float* __restrict__ gu,
    int* __restrict__ cnt, int2* __restrict__ elle,
    float* __restrict__ ego) {
    __shared__ __align__(16) char smem[SM_TOTAL];
    int blk = blockIdx.x;
    int t = threadIdx.x;

    if (blk < GEMM_BLOCKS) {
        // ---- item GEMM tile: 3-term bf16-split WMMA
        __nv_bfloat16 (*AsH)[LDA] = (__nv_bfloat16(*)[LDA])(smem + SM_AS_HI);
        __nv_bfloat16 (*AsL)[LDA] = (__nv_bfloat16(*)[LDA])(smem + SM_AS_LO);
        __nv_bfloat16 (*WsH)[LDW] = (__nv_bfloat16(*)[LDW])(smem + SM_WS_HI);
        __nv_bfloat16 (*WsL)[LDW] = (__nv_bfloat16(*)[LDW])(smem + SM_WS_LO);

        int w = t >> 5;
        int lane = t & 31;
        int r0 = blk * BM;

        wmma::fragment<wmma::accumulator, 16, 16, 16, float> cfrag[4];
        #pragma unroll
        for (int nf = 0; nf < 4; nf++) wmma::fill_fragment(cfrag[nf], 0.0f);

        int ar = t >> 1,  ac = (t & 1) * 16;
        int wr = t >> 2,  wc = (t & 3) * 8;

        for (int k0 = 0; k0 < F_DIM; k0 += GK) {
            {
                int gr = r0 + ar;
                if (gr < I_NUM) {
                    const float4* src = (const float4*)(A + (size_t)gr * F_DIM + k0 + ac);
                    #pragma unroll
                    for (int s = 0; s < 4; s++) {
                        float4 v = __ldg(src + s);
                        split_store(&AsH[ar][ac + s * 4],     &AsL[ar][ac + s * 4],     v.x);
                        split_store(&AsH[ar][ac + s * 4 + 1], &AsL[ar][ac + s * 4 + 1], v.y);
                        split_store(&AsH[ar][ac + s * 4 + 2], &AsL[ar][ac + s * 4 + 2], v.z);
                        split_store(&AsH[ar][ac + s * 4 + 3], &AsL[ar][ac + s * 4 + 3], v.w);
                    }
                } else {
                    #pragma unroll
                    for (int s = 0; s < 16; s++) {
                        AsH[ar][ac + s] = __float2bfloat16(0.f);
                        AsL[ar][ac + s] = __float2bfloat16(0.f);
                    }
                }
            }
            {
                const float4* src = (const float4*)(W + (size_t)wr * F_DIM + k0 + wc);
                #pragma unroll
                for (int s = 0; s < 2; s++) {
                    float4 v = __ldg(src + s);
                    split_store(&WsH[wr][wc + s * 4],     &WsL[wr][wc + s * 4],     v.x);
                    split_store(&WsH[wr][wc + s * 4 + 1], &WsL[wr][wc + s * 4 + 1], v.y);
                    split_store(&WsH[wr][wc + s * 4 + 2], &WsL[wr][wc + s * 4 + 2], v.z);
                    split_store(&WsH[wr][wc + s * 4 + 3], &WsL[wr][wc + s * 4 + 3], v.w);
                }
            }
            __syncthreads();

            #pragma unroll
            for (int kk = 0; kk < GK; kk += 16) {
                wmma::fragment<wmma::matrix_a, 16, 16, 16, __nv_bfloat16, wmma::row_major> aH, aL;
                wmma::load_matrix_sync(aH, &AsH[w * 16][kk], LDA);
                wmma::load_matrix_sync(aL, &AsL[w * 16][kk], LDA);
                #pragma unroll
                for (int nf = 0; nf < 4; nf++) {
                    wmma::fragment<wmma::matrix_b, 16, 16, 16, __nv_bfloat16, wmma::col_major> bH, bL;
                    wmma::load_matrix_sync(bH, &WsH[nf * 16][kk], LDW);
                    wmma::load_matrix_sync(bL, &WsL[nf * 16][kk], LDW);
                    wmma::mma_sync(cfrag[nf], aH, bH, cfrag[nf]);
                    wmma::mma_sync(cfrag[nf], aH, bL, cfrag[nf]);
                    wmma::mma_sync(cfrag[nf], aL, bH, cfrag[nf]);
                }
            }
            __syncthreads();
        }

        float (*Os)[16][D] = (float(*)[16][D])smem;
        #pragma unroll
        for (int nf = 0; nf < 4; nf++)
            wmma::store_matrix_sync(&Os[w][0][nf * 16], cfrag[nf], D, wmma::mem_row_major);
        __syncwarp();

        for (int idx = lane; idx < 16 * D; idx += 32) {
            int i = idx >> 6;
            int n = idx & 63;
            int r = r0 + w * 16 + i;
            if (r < I_NUM) {
                float c = Os[w][i][n];
                float sn = gi[n] + gi[D + n] + gi[2 * D + n];
                ego[(size_t)(U_NUM + r) * D + n] = tanh_fast(c + bias[n]) + sn;
            }
        }
    } else if (blk < GEMM_BLOCKS + BUILD_BLOCKS) {
        // ---- ELL build, grid-stride over edges
        int base = (blk - GEMM_BLOCKS) * 256 + t;
        for (int e = base; e < E_NUM; e += BUILD_BLOCKS * 256) {
            int r = __ldg(rows + e);
            int slot = atomicAdd(cnt + r, 1);
            if (slot < ELL_W) {
                int2 p;
                p.x = __ldg(cols + e);
                p.y = __float_as_int(__ldg(vals + e));
                elle[(size_t)r * ELL_W + slot] = p;
            }
        }
    } else {
        // ---- user ego init, grid-stride over users (warp per user)
        int wbase = (blk - GEMM_BLOCKS - BUILD_BLOCKS) * 8 + (t >> 5);
        int lane = t & 31;
        int d0 = lane * 2;
        float s0 = gu[d0]     + gu[D + d0]     + gu[2 * D + d0];
        float s1 = gu[d0 + 1] + gu[D + d0 + 1] + gu[2 * D + d0 + 1];
        for (int u = wbase; u < U_NUM; u += USER_BLOCKS * 8) {
            float2 v = ((const float2*)(user_fea + (size_t)u * D))[lane];
            v.x += s0; v.y += s1;
            ((float2*)(ego + (size_t)u * D))[lane] = v;
        }
    }
}

// ---------------- layer core: y_row = w * (A x)_row  (half-warp per row)
template <bool FINAL>
__global__ __launch_bounds__(256) void k_layer_t(
    const float* __restrict__ x, float* __restrict__ y,
    const int* __restrict__ cnt, const int2* __restrict__ elle,
    const float* __restrict__ ego,
    const float* __restrict__ y0, const float* __restrict__ y1,
    const float* __restrict__ y2) {
    int warp = (blockIdx.x * blockDim.x + threadIdx.x) >> 5;
    int lane = threadIdx.x & 31;
    int half = lane >> 4;
    int hl   = lane & 15;
    int row  = warp * 2 + half;
    if (row >= N_NUM) return;

    int c = min(__ldg(cnt + row), ELL_W);
    const int4* ep4 = (const int4*)(elle + (size_t)row * ELL_W);
    float4 acc = make_float4(0.f, 0.f, 0.f, 0.f);

    for (int b = 0; b < c; b += 8) {
        int q = b >> 1;
        int4 q0 = __ldg(ep4 + q);
        int4 q1 = __ldg(ep4 + q + 1);
        int4 q2 = __ldg(ep4 + q + 2);
        int4 q3 = __ldg(ep4 + q + 3);
        float4 x0 = __ldg((const float4*)(x + (size_t)q0.x * D) + hl);
        float4 x1 = __ldg((const float4*)(x + (size_t)q0.z * D) + hl);
        float4 x2 = __ldg((const float4*)(x + (size_t)q1.x * D) + hl);
        float4 x3 = __ldg((const float4*)(x + (size_t)q1.z * D) + hl);
        float4 x4 = __ldg((const float4*)(x + (size_t)q2.x * D) + hl);
        float4 x5 = __ldg((const float4*)(x + (size_t)q2.z * D) + hl);
        float4 x6 = __ldg((const float4*)(x + (size_t)q3.x * D) + hl);
        float4 x7 = __ldg((const float4*)(x + (size_t)q3.z * D) + hl);
        float v0 = __int_as_float(q0.y), v1 = __int_as_float(q0.w);
        float v2 = __int_as_float(q1.y), v3 = __int_as_float(q1.w);
        float v4 = __int_as_float(q2.y), v5 = __int_as_float(q2.w);
        float v6 = __int_as_float(q3.y), v7 = __int_as_float(q3.w);
        acc.x = fmaf(v0, x0.x, acc.x); acc.y = fmaf(v0, x0.y, acc.y);
        acc.z = fmaf(v0, x0.z, acc.z); acc.w = fmaf(v0, x0.w, acc.w);
        acc.x = fmaf(v1, x1.x, acc.x); acc.y = fmaf(v1, x1.y, acc.y);
        acc.z = fmaf(v1, x1.z, acc.z); acc.w = fmaf(v1, x1.w, acc.w);
        acc.x = fmaf(v2, x2.x, acc.x); acc.y = fmaf(v2, x2.y, acc.y);
        acc.z = fmaf(v2, x2.z, acc.z); acc.w = fmaf(v2, x2.w, acc.w);
        acc.x = fmaf(v3, x3.x, acc.x); acc.y = fmaf(v3, x3.y, acc.y);
        acc.z = fmaf(v3, x3.z, acc.z); acc.w = fmaf(v3, x3.w, acc.w);
        acc.x = fmaf(v4, x4.x, acc.x); acc.y = fmaf(v4, x4.y, acc.y);
        acc.z = fmaf(v4, x4.z, acc.z); acc.w = fmaf(v4, x4.w, acc.w);
        acc.x = fmaf(v5, x5.x, acc.x); acc.y = fmaf(v5, x5.y, acc.y);
        acc.z = fmaf(v5, x5.z, acc.z); acc.w = fmaf(v5, x5.w, acc.w);
        acc.x = fmaf(v6, x6.x, acc.x); acc.y = fmaf(v6, x6.y, acc.y);
        acc.z = fmaf(v6, x6.z, acc.z); acc.w = fmaf(v6, x6.w, acc.w);
        acc.x = fmaf(v7, x7.x, acc.x); acc.y = fmaf(v7, x7.y, acc.y);
        acc.z = fmaf(v7, x7.z, acc.z); acc.w = fmaf(v7, x7.w, acc.w);
    }

    size_t base = (size_t)row * D;
    float4 ev = __ldg((const float4*)(ego + base) + hl);
    float dot = acc.x * ev.x + acc.y * ev.y + acc.z * ev.z + acc.w * ev.w;
    float ssy = acc.x * acc.x + acc.y * acc.y + acc.z * acc.z + acc.w * acc.w;
    float sse = ev.x * ev.x + ev.y * ev.y + ev.z * ev.z + ev.w * ev.w;
    #pragma unroll
    for (int o = 8; o; o >>= 1) {
        dot += __shfl_xor_sync(0xffffffffu, dot, o);
        ssy += __shfl_xor_sync(0xffffffffu, ssy, o);
        sse += __shfl_xor_sync(0xffffffffu, sse, o);
    }
    float w = dot / (fmaxf(sqrtf(ssy), EPS) * fmaxf(sqrtf(sse), EPS));
    acc.x *= w; acc.y *= w; acc.z *= w; acc.w *= w;

    if (FINAL) {
        float4 a = __ldg((const float4*)(y0 + base) + hl);
        float4 b = __ldg((const float4*)(y1 + base) + hl);
        float4 cc = __ldg((const float4*)(y2 + base) + hl);
        acc.x += ev.x + a.x + b.x + cc.x;
        acc.y += ev.y + a.y + b.y + cc.y;
        acc.z += ev.z + a.z + b.z + cc.z;
        acc.w += ev.w + a.w + b.w + cc.w;
    }
    ((float4*)(y + base))[hl] = acc;
}

extern "C" void kernel_launch(void* const* d_in, const int* in_sizes, int n_in,
                              void* d_out, int out_size) {
    const int*   adj_row  = (const int*)d_in[0];
    const int*   adj_col  = (const int*)d_in[1];
    const float* adj_val  = (const float*)d_in[2];
    const float* user_fea = (const float*)d_in[3];
    const float* item_fea = (const float*)d_in[4];
    const float* g_emb_u  = (const float*)d_in[5];
    const float* g_emb_i  = (const float*)d_in[6];
    const float* mlp_w    = (const float*)d_in[7];
    const float* mlp_b    = (const float*)d_in[8];
    float* acc = (float*)d_out;

    float *ego_p, *b0, *b1, *b2;
    int *cnt_p; int2 *elle_p;
    cudaGetSymbolAddress((void**)&ego_p,  g_ego);
    cudaGetSymbolAddress((void**)&b0,     g_buf0);
    cudaGetSymbolAddress((void**)&b1,     g_buf1);
    cudaGetSymbolAddress((void**)&b2,     g_buf2);
    cudaGetSymbolAddress((void**)&cnt_p,  g_cnt);
    cudaGetSymbolAddress((void**)&elle_p, g_elle);

    cudaMemsetAsync(cnt_p, 0, N_NUM * sizeof(int));
    k_preamble<<<PRE_BLOCKS, 256>>>(item_fea, mlp_w, mlp_b, g_emb_i,
                                    adj_row, adj_col, adj_val,
                                    user_fea, g_emb_u,
                                    cnt_p, elle_p, ego_p);

    int lgrid = (N_NUM / 2 + 7) / 8;
    k_layer_t<false><<<lgrid, 256>>>(ego_p, b0, cnt_p, elle_p, ego_p, b0, b1, b2);
    k_layer_t<false><<<lgrid, 256>>>(b0,    b1, cnt_p, elle_p, ego_p, b0, b1, b2);
    k_layer_t<false><<<lgrid, 256>>>(b1,    b2, cnt_p, elle_p, ego_p, b0, b1, b2);
    k_layer_t<true><<<lgrid, 256>>>(b2,    acc, cnt_p, elle_p, ego_p, b0, b1, b2);
}

// round 12
// speedup vs baseline: 2.6374x; 1.0140x over previous
#include <cuda_runtime.h>
#include <cuda_bf16.h>
#include <mma.h>
#include <math.h>
#include <stdint.h>

using namespace nvcuda;

#define U_NUM 100000
#define I_NUM 50000
#define N_NUM 150000
#define E_NUM 1200000
#define D 64
#define F_DIM 384
#define EPS 1e-8f
#define ELL_W 64

// Scratch (allocation-free rule: __device__ globals; zero-initialized at load)
__device__ float g_ego[(size_t)N_NUM * D];
__device__ float g_buf0[(size_t)N_NUM * D];
__device__ float g_buf1[(size_t)N_NUM * D];
__device__ float g_buf2[(size_t)N_NUM * D];
__device__ int   g_cnt[N_NUM];
__device__ int2  g_elle[(size_t)N_NUM * ELL_W];   // packed (col, val-bits); tail slots stay 0

__device__ __forceinline__ float tanh_fast(float x) {
    float r;
    asm("tanh.approx.f32 %0, %1;" : "=f"(r) : "f"(x));
    return r;
}

// ---- L2 cache-hint policies (createpolicy + cache_hint form; v4.f32-compatible)
__device__ __forceinline__ uint64_t mk_policy_last() {
    uint64_t p;
    asm("createpolicy.fractional.L2::evict_last.b64 %0, 1.0;" : "=l"(p));
    return p;
}
__device__ __forceinline__ uint64_t mk_policy_first() {
    uint64_t p;
    asm("createpolicy.fractional.L2::evict_first.b64 %0, 1.0;" : "=l"(p));
    return p;
}
__device__ __forceinline__ float4 ldg_f4_pol(const float4* p, uint64_t pol) {
    float4 v;
    asm("ld.global.nc.L2::cache_hint.v4.f32 {%0,%1,%2,%3}, [%4], %5;"
        : "=f"(v.x), "=f"(v.y), "=f"(v.z), "=f"(v.w) : "l"(p), "l"(pol));
    return v;
}
__device__ __forceinline__ int4 ldg_i4_pol(const int4* p, uint64_t pol) {
    int4 v;
    asm("ld.global.nc.L2::cache_hint.v4.b32 {%0,%1,%2,%3}, [%4], %5;"
        : "=r"(v.x), "=r"(v.y), "=r"(v.z), "=r"(v.w) : "l"(p), "l"(pol));
    return v;
}
__device__ __forceinline__ void stg_f4_pol(float4* p, float4 v, uint64_t pol) {
    asm volatile("st.global.L2::cache_hint.v4.f32 [%0], {%1,%2,%3,%4}, %5;"
                 :: "l"(p), "f"(v.x), "f"(v.y), "f"(v.z), "f"(v.w), "l"(pol) : "memory");
}

// ---------------- fused preamble: [gemm tiles | ELL build | user init], one kernel
#define BM 128
#define GK 32
#define LDA 40
#define LDW 40

#define GEMM_BLOCKS ((I_NUM + BM - 1) / BM)   // 391
#define BUILD_BLOCKS 320
#define USER_BLOCKS  320
#define PRE_BLOCKS (GEMM_BLOCKS + BUILD_BLOCKS + USER_BLOCKS)

#define SM_AS_HI 0
#define SM_AS_LO (SM_AS_HI + BM * LDA * 2)            // 10240
#define SM_WS_HI (SM_AS_LO + BM * LDA * 2)            // 20480
#define SM_WS_LO (SM_WS_HI + D * LDW * 2)             // 25600
#define SM_MAIN  (SM_WS_LO + D * LDW * 2)             // 30720
#define SM_OS_SZ (8 * 16 * D * 4)                     // 32768
#define SM_TOTAL (SM_OS_SZ > SM_MAIN ? SM_OS_SZ : SM_MAIN)

__device__ __forceinline__ void split_store(__nv_bfloat16* hi, __nv_bfloat16* lo, float v) {
    __nv_bfloat16 h = __float2bfloat16(v);
    *hi = h;
    *lo = __float2bfloat16(v - __bfloat162float(h));
}

__global__ __launch_bounds__(256) void k_preamble(
    const float* __restrict__ A,     // item_fea [I_NUM, F_DIM]
    const float* __restrict__ W,     // mlp_w [D, F_DIM]
    const float* __restrict__ bias,
    const float* __restrict__ gi,
    const int* __restrict__ rows, const int* __restrict__ cols,
    const float* __restrict__ vals,
    const float* __restrict__ user_fea,
    const float* __restrict__ gu,
    int* __restrict__ cnt, int2* __restrict__ elle,
    float* __restrict__ ego) {
    __shared__ __align__(16) char smem[SM_TOTAL];
    int blk = blockIdx.x;
    int t = threadIdx.x;

    if (blk < GEMM_BLOCKS) {
        __nv_bfloat16 (*AsH)[LDA] = (__nv_bfloat16(*)[LDA])(smem + SM_AS_HI);
        __nv_bfloat16 (*AsL)[LDA] = (__nv_bfloat16(*)[LDA])(smem + SM_AS_LO);
        __nv_bfloat16 (*WsH)[LDW] = (__nv_bfloat16(*)[LDW])(smem + SM_WS_HI);
        __nv_bfloat16 (*WsL)[LDW] = (__nv_bfloat16(*)[LDW])(smem + SM_WS_LO);

        int w = t >> 5;
        int lane = t & 31;
        int r0 = blk * BM;

        wmma::fragment<wmma::accumulator, 16, 16, 16, float> cfrag[4];
        #pragma unroll
        for (int nf = 0; nf < 4; nf++) wmma::fill_fragment(cfrag[nf], 0.0f);

        int ar = t >> 1,  ac = (t & 1) * 16;
        int wr = t >> 2,  wc = (t & 3) * 8;

        for (int k0 = 0; k0 < F_DIM; k0 += GK) {
            {
                int gr = r0 + ar;
                if (gr < I_NUM) {
                    const float4* src = (const float4*)(A + (size_t)gr * F_DIM + k0 + ac);
                    #pragma unroll
                    for (int s = 0; s < 4; s++) {
                        float4 v = __ldg(src + s);
                        split_store(&AsH[ar][ac + s * 4],     &AsL[ar][ac + s * 4],     v.x);
                        split_store(&AsH[ar][ac + s * 4 + 1], &AsL[ar][ac + s * 4 + 1], v.y);
                        split_store(&AsH[ar][ac + s * 4 + 2], &AsL[ar][ac + s * 4 + 2], v.z);
                        split_store(&AsH[ar][ac + s * 4 + 3], &AsL[ar][ac + s * 4 + 3], v.w);
                    }
                } else {
                    #pragma unroll
                    for (int s = 0; s < 16; s++) {
                        AsH[ar][ac + s] = __float2bfloat16(0.f);
                        AsL[ar][ac + s] = __float2bfloat16(0.f);
                    }
                }
            }
            {
                const float4* src = (const float4*)(W + (size_t)wr * F_DIM + k0 + wc);
                #pragma unroll
                for (int s = 0; s < 2; s++) {
                    float4 v = __ldg(src + s);
                    split_store(&WsH[wr][wc + s * 4],     &WsL[wr][wc + s * 4],     v.x);
                    split_store(&WsH[wr][wc + s * 4 + 1], &WsL[wr][wc + s * 4 + 1], v.y);
                    split_store(&WsH[wr][wc + s * 4 + 2], &WsL[wr][wc + s * 4 + 2], v.z);
                    split_store(&WsH[wr][wc + s * 4 + 3], &WsL[wr][wc + s * 4 + 3], v.w);
                }
            }
            __syncthreads();

            #pragma unroll
            for (int kk = 0; kk < GK; kk += 16) {
                wmma::fragment<wmma::matrix_a, 16, 16, 16, __nv_bfloat16, wmma::row_major> aH, aL;
                wmma::load_matrix_sync(aH, &AsH[w * 16][kk], LDA);
                wmma::load_matrix_sync(aL, &AsL[w * 16][kk], LDA);
                #pragma unroll
                for (int nf = 0; nf < 4; nf++) {
                    wmma::fragment<wmma::matrix_b, 16, 16, 16, __nv_bfloat16, wmma::col_major> bH, bL;
                    wmma::load_matrix_sync(bH, &WsH[nf * 16][kk], LDW);
                    wmma::load_matrix_sync(bL, &WsL[nf * 16][kk], LDW);
                    wmma::mma_sync(cfrag[nf], aH, bH, cfrag[nf]);
                    wmma::mma_sync(cfrag[nf], aH, bL, cfrag[nf]);
                    wmma::mma_sync(cfrag[nf], aL, bH, cfrag[nf]);
                }
            }
            __syncthreads();
        }

        float (*Os)[16][D] = (float(*)[16][D])smem;
        #pragma unroll
        for (int nf = 0; nf < 4; nf++)
            wmma::store_matrix_sync(&Os[w][0][nf * 16], cfrag[nf], D, wmma::mem_row_major);
        __syncwarp();

        for (int idx = lane; idx < 16 * D; idx += 32) {
            int i = idx >> 6;
            int n = idx & 63;
            int r = r0 + w * 16 + i;
            if (r < I_NUM) {
                float c = Os[w][i][n];
                float sn = gi[n] + gi[D + n] + gi[2 * D + n];
                ego[(size_t)(U_NUM + r) * D + n] = tanh_fast(c + bias[n]) + sn;
            }
        }
    } else if (blk < GEMM_BLOCKS + BUILD_BLOCKS) {
        int base = (blk - GEMM_BLOCKS) * 256 + t;
        for (int e = base; e < E_NUM; e += BUILD_BLOCKS * 256) {
            int r = __ldg(rows + e);
            int slot = atomicAdd(cnt + r, 1);
            if (slot < ELL_W) {
                int2 p;
                p.x = __ldg(cols + e);
                p.y = __float_as_int(__ldg(vals + e));
                elle[(size_t)r * ELL_W + slot] = p;
            }
        }
    } else {
        int wbase = (blk - GEMM_BLOCKS - BUILD_BLOCKS) * 8 + (t >> 5);
        int lane = t & 31;
        int d0 = lane * 2;
        float s0 = gu[d0]     + gu[D + d0]     + gu[2 * D + d0];
        float s1 = gu[d0 + 1] + gu[D + d0 + 1] + gu[2 * D + d0 + 1];
        for (int u = wbase; u < U_NUM; u += USER_BLOCKS * 8) {
            float2 v = ((const float2*)(user_fea + (size_t)u * D))[lane];
            v.x += s0; v.y += s1;
            ((float2*)(ego + (size_t)u * D))[lane] = v;
        }
    }
}

// ---------------- layer core: y_row = w * (A x)_row  (half-warp per row)
// L2 policy: x gathers evict_last (high reuse); ego/ELL evict_first (streaming);
// y stores evict_last (becomes next layer's x).
template <bool FINAL>
__global__ __launch_bounds__(256) void k_layer_t(
    const float* __restrict__ x, float* __restrict__ y,
    const int* __restrict__ cnt, const int2* __restrict__ elle,
    const float* __restrict__ ego,
    const float* __restrict__ y0, const float* __restrict__ y1,
    const float* __restrict__ y2) {
    int warp = (blockIdx.x * blockDim.x + threadIdx.x) >> 5;
    int lane = threadIdx.x & 31;
    int half = lane >> 4;
    int hl   = lane & 15;
    int row  = warp * 2 + half;
    if (row >= N_NUM) return;

    uint64_t pL = mk_policy_last();
    uint64_t pF = mk_policy_first();

    int c = min(__ldg(cnt + row), ELL_W);
    const int4* ep4 = (const int4*)(elle + (size_t)row * ELL_W);
    float4 acc = make_float4(0.f, 0.f, 0.f, 0.f);

    for (int b = 0; b < c; b += 8) {
        int q = b >> 1;
        int4 q0 = ldg_i4_pol(ep4 + q,     pF);
        int4 q1 = ldg_i4_pol(ep4 + q + 1, pF);
        int4 q2 = ldg_i4_pol(ep4 + q + 2, pF);
        int4 q3 = ldg_i4_pol(ep4 + q + 3, pF);
        float4 x0 = ldg_f4_pol((const float4*)(x + (size_t)q0.x * D) + hl, pL);
        float4 x1 = ldg_f4_pol((const float4*)(x + (size_t)q0.z * D) + hl, pL);
        float4 x2 = ldg_f4_pol((const float4*)(x + (size_t)q1.x * D) + hl, pL);
        float4 x3 = ldg_f4_pol((const float4*)(x + (size_t)q1.z * D) + hl, pL);
        float4 x4 = ldg_f4_pol((const float4*)(x + (size_t)q2.x * D) + hl, pL);
        float4 x5 = ldg_f4_pol((const float4*)(x + (size_t)q2.z * D) + hl, pL);
        float4 x6 = ldg_f4_pol((const float4*)(x + (size_t)q3.x * D) + hl, pL);
        float4 x7 = ldg_f4_pol((const float4*)(x + (size_t)q3.z * D) + hl, pL);
        float v0 = __int_as_float(q0.y), v1 = __int_as_float(q0.w);
        float v2 = __int_as_float(q1.y), v3 = __int_as_float(q1.w);
        float v4 = __int_as_float(q2.y), v5 = __int_as_float(q2.w);
        float v6 = __int_as_float(q3.y), v7 = __int_as_float(q3.w);
        acc.x = fmaf(v0, x0.x, acc.x); acc.y = fmaf(v0, x0.y, acc.y);
        acc.z = fmaf(v0, x0.z, acc.z); acc.w = fmaf(v0, x0.w, acc.w);
        acc.x = fmaf(v1, x1.x, acc.x); acc.y = fmaf(v1, x1.y, acc.y);
        acc.z = fmaf(v1, x1.z, acc.z); acc.w = fmaf(v1, x1.w, acc.w);
        acc.x = fmaf(v2, x2.x, acc.x); acc.y = fmaf(v2, x2.y, acc.y);
        acc.z = fmaf(v2, x2.z, acc.z); acc.w = fmaf(v2, x2.w, acc.w);
        acc.x = fmaf(v3, x3.x, acc.x); acc.y = fmaf(v3, x3.y, acc.y);
        acc.z = fmaf(v3, x3.z, acc.z); acc.w = fmaf(v3, x3.w, acc.w);
        acc.x = fmaf(v4, x4.x, acc.x); acc.y = fmaf(v4, x4.y, acc.y);
        acc.z = fmaf(v4, x4.z, acc.z); acc.w = fmaf(v4, x4.w, acc.w);
        acc.x = fmaf(v5, x5.x, acc.x); acc.y = fmaf(v5, x5.y, acc.y);
        acc.z = fmaf(v5, x5.z, acc.z); acc.w = fmaf(v5, x5.w, acc.w);
        acc.x = fmaf(v6, x6.x, acc.x); acc.y = fmaf(v6, x6.y, acc.y);
        acc.z = fmaf(v6, x6.z, acc.z); acc.w = fmaf(v6, x6.w, acc.w);
        acc.x = fmaf(v7, x7.x, acc.x); acc.y = fmaf(v7, x7.y, acc.y);
        acc.z = fmaf(v7, x7.z, acc.z); acc.w = fmaf(v7, x7.w, acc.w);
    }

    size_t base = (size_t)row * D;
    float4 ev = ldg_f4_pol((const float4*)(ego + base) + hl, pF);
    float dot = acc.x * ev.x + acc.y * ev.y + acc.z * ev.z + acc.w * ev.w;
    float ssy = acc.x * acc.x + acc.y * acc.y + acc.z * acc.z + acc.w * acc.w;
    float sse = ev.x * ev.x + ev.y * ev.y + ev.z * ev.z + ev.w * ev.w;
    #pragma unroll
    for (int o = 8; o; o >>= 1) {
        dot += __shfl_xor_sync(0xffffffffu, dot, o);
        ssy += __shfl_xor_sync(0xffffffffu, ssy, o);
        sse += __shfl_xor_sync(0xffffffffu, sse, o);
    }
    float w = dot / (fmaxf(sqrtf(ssy), EPS) * fmaxf(sqrtf(sse), EPS));
    acc.x *= w; acc.y *= w; acc.z *= w; acc.w *= w;

    if (FINAL) {
        float4 a = ldg_f4_pol((const float4*)(y0 + base) + hl, pF);
        float4 b = ldg_f4_pol((const float4*)(y1 + base) + hl, pF);
        float4 cc = ldg_f4_pol((const float4*)(y2 + base) + hl, pF);
        acc.x += ev.x + a.x + b.x + cc.x;
        acc.y += ev.y + a.y + b.y + cc.y;
        acc.z += ev.z + a.z + b.z + cc.z;
        acc.w += ev.w + a.w + b.w + cc.w;
        ((float4*)(y + base))[hl] = acc;   // final output: default policy
    } else {
        stg_f4_pol((float4*)(y + base) + hl, acc, pL);
    }
}

extern "C" void kernel_launch(void* const* d_in, const int* in_sizes, int n_in,
                              void* d_out, int out_size) {
    const int*   adj_row  = (const int*)d_in[0];
    const int*   adj_col  = (const int*)d_in[1];
    const float* adj_val  = (const float*)d_in[2];
    const float* user_fea = (const float*)d_in[3];
    const float* item_fea = (const float*)d_in[4];
    const float* g_emb_u  = (const float*)d_in[5];
    const float* g_emb_i  = (const float*)d_in[6];
    const float* mlp_w    = (const float*)d_in[7];
    const float* mlp_b    = (const float*)d_in[8];
    float* acc = (float*)d_out;

    float *ego_p, *b0, *b1, *b2;
    int *cnt_p; int2 *elle_p;
    cudaGetSymbolAddress((void**)&ego_p,  g_ego);
    cudaGetSymbolAddress((void**)&b0,     g_buf0);
    cudaGetSymbolAddress((void**)&b1,     g_buf1);
    cudaGetSymbolAddress((void**)&b2,     g_buf2);
    cudaGetSymbolAddress((void**)&cnt_p,  g_cnt);
    cudaGetSymbolAddress((void**)&elle_p, g_elle);

    cudaMemsetAsync(cnt_p, 0, N_NUM * sizeof(int));
    k_preamble<<<PRE_BLOCKS, 256>>>(item_fea, mlp_w, mlp_b, g_emb_i,
                                    adj_row, adj_col, adj_val,
                                    user_fea, g_emb_u,
                                    cnt_p, elle_p, ego_p);

    int lgrid = (N_NUM / 2 + 7) / 8;
    k_layer_t<false><<<lgrid, 256>>>(ego_p, b0, cnt_p, elle_p, ego_p, b0, b1, b2);
    k_layer_t<false><<<lgrid, 256>>>(b0,    b1, cnt_p, elle_p, ego_p, b0, b1, b2);
    k_layer_t<false><<<lgrid, 256>>>(b1,    b2, cnt_p, elle_p, ego_p, b0, b1, b2);
    k_layer_t<true><<<lgrid, 256>>>(b2,    acc, cnt_p, elle_p, ego_p, b0, b1, b2);
}